// round 1
// baseline (speedup 1.0000x reference)
#include <cuda_runtime.h>
#include <cstddef>

// ---------------------------------------------------------------------------
// Problem constants (shapes fixed by the reference setup_inputs)
// ---------------------------------------------------------------------------
#define BATCH    64
#define SPOINTS  128
#define MROWS    (BATCH * SPOINTS)     // 8192 rows for every GEMM
#define NOUT     1024                  // all blocks project to 1024 channels
#define CHUNK    (8388608)             // elements per f0..f4 tensor (all equal)
#define SLOPE    0.2f
#define EPSV     1e-5f

// ---------------------------------------------------------------------------
// Scratch (device globals: allocation-free per harness rules)
// ---------------------------------------------------------------------------
__device__ float g_ybuf[MROWS * NOUT];   // 32 MB: current-stage GEMM output
__device__ float g_acc [MROWS * NOUT];   // 32 MB: running sum f4 + branches
__device__ int   g_rows[4 * MROWS];      // gathered global row indices per branch
__device__ float g_stats[5 * 2 * NOUT];  // per stage: [sum(1024) | sumsq(1024)]

// ---------------------------------------------------------------------------
// Index chain: idx24 = FPS_2[FPS_3], idx14 = FPS_1[idx24], idx04 = FPS_0[idx14]
// Store as GLOBAL row indices (b * N_level + idx) so gathers are flat.
// ---------------------------------------------------------------------------
__global__ void idx_kernel(const int* __restrict__ F0, const int* __restrict__ F1,
                           const int* __restrict__ F2, const int* __restrict__ F3,
                           int* __restrict__ rows)
{
    int i = blockIdx.x * blockDim.x + threadIdx.x;
    if (i >= MROWS) return;
    int b  = i >> 7;                 // i / 128
    int i3 = F3[i];                  // index into N3 = 256
    int i2 = F2[(b << 8) + i3];      // index into N2 = 512
    int i1 = F1[(b << 9) + i2];      // index into N1 = 1024
    int i0 = F0[(b << 10) + i1];     // index into N0 = 2048
    rows[0 * MROWS + i] = (b << 11) + i0;  // rows into f0 [B*2048]
    rows[1 * MROWS + i] = (b << 10) + i1;  // rows into f1 [B*1024]
    rows[2 * MROWS + i] = (b << 9)  + i2;  // rows into f2 [B*512]
    rows[3 * MROWS + i] = (b << 8)  + i3;  // rows into f3 [B*256]
}

// ---------------------------------------------------------------------------
// acc = f4  (float4 copy)
// ---------------------------------------------------------------------------
__global__ void acc_init_kernel(const float4* __restrict__ f4, float4* __restrict__ acc)
{
    int i = blockIdx.x * blockDim.x + threadIdx.x;
    acc[i] = f4[i];
}

// ---------------------------------------------------------------------------
// Tiled SGEMM with optional row-gather on A.
//   Y[m, n] = sum_k X[rowA(m), k] * W[n, k] + bias[n]
// BM = BN = 128, BK = 8, 256 threads, 8x8 register microtile per thread.
// Both A and W are K-major (NT gemm) so loads are contiguous float4 along K.
// ---------------------------------------------------------------------------
__global__ __launch_bounds__(256) void gemm_kernel(
    const float* __restrict__ X, const float* __restrict__ W,
    const float* __restrict__ bias, const int* __restrict__ rows,
    int K, float* __restrict__ Y)
{
    __shared__ float As[8][128];
    __shared__ float Bs[8][128];

    const int tid = threadIdx.x;
    const int bm  = blockIdx.y * 128;
    const int bn  = blockIdx.x * 128;

    // loader mapping: each thread loads one float4 (row = tid>>1, k-quad = tid&1)
    const int lr = tid >> 1;
    const int lk = (tid & 1) * 4;

    // compute mapping: 16x16 thread grid of 8x8 microtiles
    const int tm = (tid >> 4) * 8;
    const int tn = (tid & 15) * 8;

    int rowA = bm + lr;
    if (rows) rowA = rows[rowA];
    const float* Ap = X + (size_t)rowA * K + lk;
    const float* Bp = W + (size_t)(bn + lr) * K + lk;

    float acc[8][8];
#pragma unroll
    for (int i = 0; i < 8; i++)
#pragma unroll
        for (int j = 0; j < 8; j++) acc[i][j] = 0.f;

    for (int k0 = 0; k0 < K; k0 += 8) {
        float4 av = *(const float4*)(Ap + k0);
        float4 bv = *(const float4*)(Bp + k0);
        __syncthreads();
        As[lk + 0][lr] = av.x; As[lk + 1][lr] = av.y;
        As[lk + 2][lr] = av.z; As[lk + 3][lr] = av.w;
        Bs[lk + 0][lr] = bv.x; Bs[lk + 1][lr] = bv.y;
        Bs[lk + 2][lr] = bv.z; Bs[lk + 3][lr] = bv.w;
        __syncthreads();

#pragma unroll
        for (int kk = 0; kk < 8; kk++) {
            float a[8], b8[8];
            *(float4*)(a)     = *(const float4*)&As[kk][tm];
            *(float4*)(a + 4) = *(const float4*)&As[kk][tm + 4];
            *(float4*)(b8)     = *(const float4*)&Bs[kk][tn];
            *(float4*)(b8 + 4) = *(const float4*)&Bs[kk][tn + 4];
#pragma unroll
            for (int i = 0; i < 8; i++)
#pragma unroll
                for (int j = 0; j < 8; j++)
                    acc[i][j] += a[i] * b8[j];
        }
    }

#pragma unroll
    for (int i = 0; i < 8; i++) {
        float* yp = Y + (size_t)(bm + tm + i) * NOUT + bn + tn;
        float4 o0, o1;
        o0.x = acc[i][0] + bias[bn + tn + 0];
        o0.y = acc[i][1] + bias[bn + tn + 1];
        o0.z = acc[i][2] + bias[bn + tn + 2];
        o0.w = acc[i][3] + bias[bn + tn + 3];
        o1.x = acc[i][4] + bias[bn + tn + 4];
        o1.y = acc[i][5] + bias[bn + tn + 5];
        o1.z = acc[i][6] + bias[bn + tn + 6];
        o1.w = acc[i][7] + bias[bn + tn + 7];
        *(float4*)yp       = o0;
        *(float4*)(yp + 4) = o1;
    }
}

// ---------------------------------------------------------------------------
// Per-channel sum / sumsq. Each block reduces 64 rows; each thread privately
// owns 4 channels (coalesced float4 row reads), then 8 global atomics.
// ---------------------------------------------------------------------------
__global__ void stats_kernel(const float* __restrict__ Y, float* __restrict__ st)
{
    const int c = threadIdx.x * 4;
    const float* p = Y + (size_t)blockIdx.x * 64 * NOUT + c;
    float s0 = 0, s1 = 0, s2 = 0, s3 = 0;
    float q0 = 0, q1 = 0, q2 = 0, q3 = 0;
#pragma unroll 4
    for (int r = 0; r < 64; r++) {
        float4 v = *(const float4*)(p + (size_t)r * NOUT);
        s0 += v.x; s1 += v.y; s2 += v.z; s3 += v.w;
        q0 += v.x * v.x; q1 += v.y * v.y; q2 += v.z * v.z; q3 += v.w * v.w;
    }
    atomicAdd(&st[c + 0], s0); atomicAdd(&st[c + 1], s1);
    atomicAdd(&st[c + 2], s2); atomicAdd(&st[c + 3], s3);
    atomicAdd(&st[NOUT + c + 0], q0); atomicAdd(&st[NOUT + c + 1], q1);
    atomicAdd(&st[NOUT + c + 2], q2); atomicAdd(&st[NOUT + c + 3], q3);
}

// Fold (mean, var, gamma, beta) into per-channel scale/shift, in place.
__global__ void finalize_stats_kernel(float* __restrict__ st,
                                      const float* __restrict__ g,
                                      const float* __restrict__ be)
{
    int c = blockIdx.x * blockDim.x + threadIdx.x;
    if (c >= NOUT) return;
    const float inv = 1.0f / (float)MROWS;
    float mean = st[c] * inv;
    float var  = st[NOUT + c] * inv - mean * mean;   // biased var, torch BN style
    float sc   = rsqrtf(var + EPSV) * g[c];
    st[c]        = sc;
    st[NOUT + c] = be[c] - mean * sc;
}

__device__ __forceinline__ float leaky(float v) { return v >= 0.f ? v : SLOPE * v; }

// acc += leakyrelu(y * sc + sh)
__global__ void norm_acc_kernel(const float4* __restrict__ Y,
                                const float* __restrict__ st,
                                float4* __restrict__ acc)
{
    int i = blockIdx.x * blockDim.x + threadIdx.x;   // over CHUNK/4 float4s
    int c = (i * 4) & (NOUT - 1);
    float4 y = Y[i];
    float4 a = acc[i];
    a.x += leaky(y.x * st[c + 0] + st[NOUT + c + 0]);
    a.y += leaky(y.y * st[c + 1] + st[NOUT + c + 1]);
    a.z += leaky(y.z * st[c + 2] + st[NOUT + c + 2]);
    a.w += leaky(y.w * st[c + 3] + st[NOUT + c + 3]);
    acc[i] = a;
}

// out = leakyrelu(y * sc + sh) + f4   (residual, final stage)
__global__ void norm_final_kernel(const float4* __restrict__ Y,
                                  const float* __restrict__ st,
                                  const float4* __restrict__ f4,
                                  float4* __restrict__ out)
{
    int i = blockIdx.x * blockDim.x + threadIdx.x;
    int c = (i * 4) & (NOUT - 1);
    float4 y = Y[i];
    float4 r = f4[i];
    float4 o;
    o.x = leaky(y.x * st[c + 0] + st[NOUT + c + 0]) + r.x;
    o.y = leaky(y.y * st[c + 1] + st[NOUT + c + 1]) + r.y;
    o.z = leaky(y.z * st[c + 2] + st[NOUT + c + 2]) + r.z;
    o.w = leaky(y.w * st[c + 3] + st[NOUT + c + 3]) + r.w;
    out[i] = o;
}

// ---------------------------------------------------------------------------
// Host launcher
// Inputs (metadata order):
//  0: num_point (int, ==128)
//  1..5:  f0,f1,f2,f3,f4               (float32)
//  6..9:  FPS_0..FPS_3                 (int32)
//  10..13: w04,b04,g04,be04
//  14..17: w14,b14,g14,be14
//  18..21: w24,b24,g24,be24
//  22..25: w34,b34,g34,be34
//  26..29: w4, b4, g4, be4
// Output: concat(f0, f1, f2, f3, f4_new) -> 5 * 8388608 floats
// ---------------------------------------------------------------------------
extern "C" void kernel_launch(void* const* d_in, const int* in_sizes, int n_in,
                              void* d_out, int out_size)
{
    (void)in_sizes; (void)n_in; (void)out_size;

    const float* f[5];
    for (int i = 0; i < 5; i++) f[i] = (const float*)d_in[1 + i];
    const int* FPS[4];
    for (int i = 0; i < 4; i++) FPS[i] = (const int*)d_in[6 + i];

    const float* w[5];  const float* bia[5];
    const float* gam[5]; const float* bet[5];
    for (int i = 0; i < 5; i++) {
        w[i]   = (const float*)d_in[10 + 4 * i + 0];
        bia[i] = (const float*)d_in[10 + 4 * i + 1];
        gam[i] = (const float*)d_in[10 + 4 * i + 2];
        bet[i] = (const float*)d_in[10 + 4 * i + 3];
    }

    float* out = (float*)d_out;

    // Resolve device-global scratch addresses.
    float *ybuf, *acc, *stats;
    int   *rows;
    cudaGetSymbolAddress((void**)&ybuf,  g_ybuf);
    cudaGetSymbolAddress((void**)&acc,   g_acc);
    cudaGetSymbolAddress((void**)&stats, g_stats);
    cudaGetSymbolAddress((void**)&rows,  g_rows);

    // 1) pass-through copies f0..f3 -> out slices
    for (int i = 0; i < 4; i++) {
        cudaMemcpyAsync(out + (size_t)i * CHUNK, f[i],
                        (size_t)CHUNK * sizeof(float),
                        cudaMemcpyDeviceToDevice, 0);
    }

    // 2) zero the stats scratch (all 5 stages)
    cudaMemsetAsync(stats, 0, 5 * 2 * NOUT * sizeof(float), 0);

    // 3) index chains
    idx_kernel<<<MROWS / 256, 256>>>(FPS[0], FPS[1], FPS[2], FPS[3], rows);

    // 4) acc = f4
    acc_init_kernel<<<CHUNK / 4 / 256, 256>>>((const float4*)f[4], (float4*)acc);

    const int Ks[4] = {64, 128, 256, 512};
    dim3 gemmGrid(NOUT / 128, MROWS / 128);
    const int n4blk = CHUNK / 4 / 256;

    // 5) four gather->linear->BN->leakyrelu branches, accumulated into acc
    for (int s = 0; s < 4; s++) {
        float* st = stats + (size_t)s * 2 * NOUT;
        gemm_kernel<<<gemmGrid, 256>>>(f[s], w[s], bia[s], rows + s * MROWS, Ks[s], ybuf);
        stats_kernel<<<MROWS / 64, 256>>>(ybuf, st);
        finalize_stats_kernel<<<4, 256>>>(st, gam[s], bet[s]);
        norm_acc_kernel<<<n4blk, 256>>>((const float4*)ybuf, st, (float4*)acc);
    }

    // 6) final block on (f4 + sum of branches), plus residual f4
    {
        float* st = stats + (size_t)4 * 2 * NOUT;
        gemm_kernel<<<gemmGrid, 256>>>(acc, w[4], bia[4], nullptr, 1024, ybuf);
        stats_kernel<<<MROWS / 64, 256>>>(ybuf, st);
        finalize_stats_kernel<<<4, 256>>>(st, gam[4], bet[4]);
        norm_final_kernel<<<n4blk, 256>>>((const float4*)ybuf, st,
                                          (const float4*)f[4],
                                          (float4*)(out + (size_t)4 * CHUNK));
    }
}

// round 3
// speedup vs baseline: 2.5259x; 2.5259x over previous
#include <cuda_runtime.h>
#include <cstdint>
#include <cstddef>

// ---------------------------------------------------------------------------
// Problem constants
// ---------------------------------------------------------------------------
#define BATCH    64
#define SPOINTS  128
#define MROWS    (BATCH * SPOINTS)     // 8192 rows for every GEMM
#define NOUT     1024
#define CHUNK    (8388608)             // elements per f0..f4 tensor
#define SLOPE    0.2f
#define EPSV     1e-5f

// ---------------------------------------------------------------------------
// Scratch (device globals: allocation-free per harness rules)
// ---------------------------------------------------------------------------
__device__ float g_ybuf[4 * MROWS * NOUT];  // 128 MB: 4 branch GEMM outputs (+ reuse)
__device__ float g_acc [MROWS * NOUT];      // 32 MB: f4 + sum of branches
__device__ int   g_rows[4 * MROWS];
__device__ float g_stats[5 * 2 * NOUT];     // per stage: [sum|sumsq] -> [scale|shift]

// ---------------------------------------------------------------------------
// Index chains
// ---------------------------------------------------------------------------
__global__ void idx_kernel(const int* __restrict__ F0, const int* __restrict__ F1,
                           const int* __restrict__ F2, const int* __restrict__ F3,
                           int* __restrict__ rows)
{
    int i = blockIdx.x * blockDim.x + threadIdx.x;
    if (i >= MROWS) return;
    int b  = i >> 7;
    int i3 = F3[i];
    int i2 = F2[(b << 8) + i3];
    int i1 = F1[(b << 9) + i2];
    int i0 = F0[(b << 10) + i1];
    rows[0 * MROWS + i] = (b << 11) + i0;
    rows[1 * MROWS + i] = (b << 10) + i1;
    rows[2 * MROWS + i] = (b << 9)  + i2;
    rows[3 * MROWS + i] = (b << 8)  + i3;
}

// ---------------------------------------------------------------------------
// tf32 warp MMA helpers
// ---------------------------------------------------------------------------
__device__ __forceinline__ void mma_tf32(float c[4], const uint32_t a[4], const uint32_t b[2])
{
    asm volatile(
        "mma.sync.aligned.m16n8k8.row.col.f32.tf32.tf32.f32 "
        "{%0,%1,%2,%3}, {%4,%5,%6,%7}, {%8,%9}, {%0,%1,%2,%3};\n"
        : "+f"(c[0]), "+f"(c[1]), "+f"(c[2]), "+f"(c[3])
        : "r"(a[0]), "r"(a[1]), "r"(a[2]), "r"(a[3]), "r"(b[0]), "r"(b[1]));
}
__device__ __forceinline__ uint32_t to_tf32(float v)
{
    uint32_t o;
    asm("cvt.rna.tf32.f32 %0, %1;" : "=r"(o) : "f"(v));
    return o;
}

// ---------------------------------------------------------------------------
// tf32 tensor-core GEMM with fused row-gather on A and fused BN statistics.
//   Y[m, n] = sum_k X[rowA(m), k] * W[n, k]        (Linear bias dropped:
//   training-mode BatchNorm subtracts the batch mean, so bias cancels exactly)
//   st[0:1024]     += per-column sums of Y
//   st[1024:2048]  += per-column sums of Y^2
// Block tile 128x128, BK=32, 256 threads = 8 warps in 2(m) x 4(n) layout,
// warp tile 64x32 = 4x4 grid of m16n8k8 MMAs.
// ---------------------------------------------------------------------------
#define LDAS 36   // padded smem row stride (floats)

__global__ __launch_bounds__(256) void gemm_mma_kernel(
    const float* __restrict__ X, const float* __restrict__ W,
    const int* __restrict__ rows, int K,
    float* __restrict__ Y, float* __restrict__ st)
{
    __shared__ float As[128][LDAS];
    __shared__ float Bs[128][LDAS];

    const int tid  = threadIdx.x;
    const int lane = tid & 31;
    const int wid  = tid >> 5;
    const int wm   = wid & 1;      // warp m offset: 64*wm
    const int wn   = wid >> 1;     // warp n offset: 32*wn
    const int bm   = blockIdx.y * 128;
    const int bn   = blockIdx.x * 128;
    const int lg   = lane >> 2;    // group id (0..7)
    const int lt   = lane & 3;     // thread-in-group (0..3)

    // Staging pointers: each thread owns 4 (row, quad) slots for A and B.
    const float* ap[4]; int arr[4], arq[4];
    const float* bp[4]; int brr[4], brq[4];
#pragma unroll
    for (int i = 0; i < 4; i++) {
        int idx = tid + 256 * i;
        int r = idx >> 3, q = idx & 7;
        int rowA = bm + r;
        if (rows) rowA = rows[rowA];
        ap[i] = X + (size_t)rowA * K + q * 4;
        arr[i] = r; arq[i] = q * 4;
        bp[i] = W + (size_t)(bn + r) * K + q * 4;
        brr[i] = r; brq[i] = q * 4;
    }

    float c[4][4][4];
#pragma unroll
    for (int mt = 0; mt < 4; mt++)
#pragma unroll
        for (int nt = 0; nt < 4; nt++)
#pragma unroll
            for (int j = 0; j < 4; j++) c[mt][nt][j] = 0.f;

    for (int k0 = 0; k0 < K; k0 += 32) {
        float4 av[4], bv[4];
#pragma unroll
        for (int i = 0; i < 4; i++) {
            av[i] = *(const float4*)(ap[i] + k0);
            bv[i] = *(const float4*)(bp[i] + k0);
        }
        __syncthreads();   // previous iteration's reads complete
#pragma unroll
        for (int i = 0; i < 4; i++) {
            float* d = &As[arr[i]][arq[i]];
            d[0] = __uint_as_float(to_tf32(av[i].x));
            d[1] = __uint_as_float(to_tf32(av[i].y));
            d[2] = __uint_as_float(to_tf32(av[i].z));
            d[3] = __uint_as_float(to_tf32(av[i].w));
            float* e = &Bs[brr[i]][brq[i]];
            e[0] = __uint_as_float(to_tf32(bv[i].x));
            e[1] = __uint_as_float(to_tf32(bv[i].y));
            e[2] = __uint_as_float(to_tf32(bv[i].z));
            e[3] = __uint_as_float(to_tf32(bv[i].w));
        }
        __syncthreads();

#pragma unroll
        for (int kk = 0; kk < 32; kk += 8) {
            uint32_t a[4][4];
#pragma unroll
            for (int mt = 0; mt < 4; mt++) {
                const float* base = &As[wm * 64 + mt * 16 + lg][kk + lt];
                a[mt][0] = __float_as_uint(base[0]);
                a[mt][1] = __float_as_uint(base[8 * LDAS]);
                a[mt][2] = __float_as_uint(base[4]);
                a[mt][3] = __float_as_uint(base[8 * LDAS + 4]);
            }
            uint32_t b[4][2];
#pragma unroll
            for (int nt = 0; nt < 4; nt++) {
                const float* base = &Bs[wn * 32 + nt * 8 + lg][kk + lt];
                b[nt][0] = __float_as_uint(base[0]);
                b[nt][1] = __float_as_uint(base[4]);
            }
#pragma unroll
            for (int mt = 0; mt < 4; mt++)
#pragma unroll
                for (int nt = 0; nt < 4; nt++)
                    mma_tf32(c[mt][nt], a[mt], b[nt]);
        }
    }

    // Epilogue: write Y (float2 stores) and accumulate fused BN statistics.
    const int row0 = bm + wm * 64 + lg;
    const int col0 = bn + wn * 32 + lt * 2;
#pragma unroll
    for (int mt = 0; mt < 4; mt++) {
#pragma unroll
        for (int nt = 0; nt < 4; nt++) {
            float2 v0 = make_float2(c[mt][nt][0], c[mt][nt][1]);
            float2 v1 = make_float2(c[mt][nt][2], c[mt][nt][3]);
            *(float2*)&Y[(size_t)(row0 + mt * 16)     * NOUT + col0 + nt * 8] = v0;
            *(float2*)&Y[(size_t)(row0 + mt * 16 + 8) * NOUT + col0 + nt * 8] = v1;
        }
    }

    // Per-column partial sums over this block's 128 rows (per warp: 64 rows).
#pragma unroll
    for (int nt = 0; nt < 4; nt++) {
        float s0 = 0.f, s1 = 0.f, q0 = 0.f, q1 = 0.f;
#pragma unroll
        for (int mt = 0; mt < 4; mt++) {
            float e0 = c[mt][nt][0], e1 = c[mt][nt][1];
            float e2 = c[mt][nt][2], e3 = c[mt][nt][3];
            s0 += e0 + e2;      s1 += e1 + e3;
            q0 += e0 * e0 + e2 * e2;
            q1 += e1 * e1 + e3 * e3;
        }
#pragma unroll
        for (int off = 4; off < 32; off <<= 1) {
            s0 += __shfl_xor_sync(0xffffffffu, s0, off);
            s1 += __shfl_xor_sync(0xffffffffu, s1, off);
            q0 += __shfl_xor_sync(0xffffffffu, q0, off);
            q1 += __shfl_xor_sync(0xffffffffu, q1, off);
        }
        if (lane < 4) {
            int col = bn + wn * 32 + nt * 8 + lane * 2;
            atomicAdd(&st[col],            s0);
            atomicAdd(&st[col + 1],        s1);
            atomicAdd(&st[NOUT + col],     q0);
            atomicAdd(&st[NOUT + col + 1], q1);
        }
    }
}

// ---------------------------------------------------------------------------
// Fold (mean, var, gamma, beta) into per-channel scale/shift, in place.
// ---------------------------------------------------------------------------
__global__ void finalize_stats_kernel(float* __restrict__ st,
                                      const float* __restrict__ g,
                                      const float* __restrict__ be)
{
    int c = blockIdx.x * blockDim.x + threadIdx.x;
    if (c >= NOUT) return;
    const float inv = 1.0f / (float)MROWS;
    float mean = st[c] * inv;
    float var  = st[NOUT + c] * inv - mean * mean;
    float sc   = rsqrtf(var + EPSV) * g[c];
    st[c]        = sc;
    st[NOUT + c] = be[c] - mean * sc;
}

__device__ __forceinline__ float leaky(float v) { return v >= 0.f ? v : SLOPE * v; }

// acc = f4 + sum_{s=0..3} leaky(y_s * sc_s + sh_s)
__global__ void norm_acc4_kernel(const float4* __restrict__ y0, const float4* __restrict__ y1,
                                 const float4* __restrict__ y2, const float4* __restrict__ y3,
                                 const float* __restrict__ st,
                                 const float4* __restrict__ f4, float4* __restrict__ acc)
{
    int i = blockIdx.x * blockDim.x + threadIdx.x;
    int c = (i * 4) & (NOUT - 1);
    float4 a = f4[i];
    const float4* ys[4] = {y0, y1, y2, y3};
#pragma unroll
    for (int s = 0; s < 4; s++) {
        const float* sp = st + (size_t)s * 2 * NOUT;
        float4 y = ys[s][i];
        a.x += leaky(y.x * sp[c + 0] + sp[NOUT + c + 0]);
        a.y += leaky(y.y * sp[c + 1] + sp[NOUT + c + 1]);
        a.z += leaky(y.z * sp[c + 2] + sp[NOUT + c + 2]);
        a.w += leaky(y.w * sp[c + 3] + sp[NOUT + c + 3]);
    }
    acc[i] = a;
}

// out = leaky(y * sc + sh) + f4
__global__ void norm_final_kernel(const float4* __restrict__ Y,
                                  const float* __restrict__ st,
                                  const float4* __restrict__ f4,
                                  float4* __restrict__ out)
{
    int i = blockIdx.x * blockDim.x + threadIdx.x;
    int c = (i * 4) & (NOUT - 1);
    float4 y = Y[i];
    float4 r = f4[i];
    float4 o;
    o.x = leaky(y.x * st[c + 0] + st[NOUT + c + 0]) + r.x;
    o.y = leaky(y.y * st[c + 1] + st[NOUT + c + 1]) + r.y;
    o.z = leaky(y.z * st[c + 2] + st[NOUT + c + 2]) + r.z;
    o.w = leaky(y.w * st[c + 3] + st[NOUT + c + 3]) + r.w;
    out[i] = o;
}

// ---------------------------------------------------------------------------
// Host launcher
// ---------------------------------------------------------------------------
extern "C" void kernel_launch(void* const* d_in, const int* in_sizes, int n_in,
                              void* d_out, int out_size)
{
    (void)in_sizes; (void)n_in; (void)out_size;

    const float* f[5];
    for (int i = 0; i < 5; i++) f[i] = (const float*)d_in[1 + i];
    const int* FPS[4];
    for (int i = 0; i < 4; i++) FPS[i] = (const int*)d_in[6 + i];

    const float* w[5]; const float* gam[5]; const float* bet[5];
    for (int i = 0; i < 5; i++) {
        w[i]   = (const float*)d_in[10 + 4 * i + 0];
        gam[i] = (const float*)d_in[10 + 4 * i + 2];
        bet[i] = (const float*)d_in[10 + 4 * i + 3];
    }

    float* out = (float*)d_out;

    float *ybuf, *acc, *stats;
    int   *rows;
    cudaGetSymbolAddress((void**)&ybuf,  g_ybuf);
    cudaGetSymbolAddress((void**)&acc,   g_acc);
    cudaGetSymbolAddress((void**)&stats, g_stats);
    cudaGetSymbolAddress((void**)&rows,  g_rows);

    // 1) pass-through copies f0..f3 -> out slices
    for (int i = 0; i < 4; i++) {
        cudaMemcpyAsync(out + (size_t)i * CHUNK, f[i],
                        (size_t)CHUNK * sizeof(float),
                        cudaMemcpyDeviceToDevice, 0);
    }

    // 2) zero stats
    cudaMemsetAsync(stats, 0, 5 * 2 * NOUT * sizeof(float), 0);

    // 3) index chains
    idx_kernel<<<MROWS / 256, 256>>>(FPS[0], FPS[1], FPS[2], FPS[3], rows);

    const int Ks[4] = {64, 128, 256, 512};
    dim3 gemmGrid(NOUT / 128, MROWS / 128);   // (8, 64)
    const int n4blk = CHUNK / 4 / 256;

    // 4) four gather->linear branches on tensor cores; stats fused in epilogue
    for (int s = 0; s < 4; s++) {
        float* yb = ybuf + (size_t)s * MROWS * NOUT;
        float* st = stats + (size_t)s * 2 * NOUT;
        gemm_mma_kernel<<<gemmGrid, 256>>>(f[s], w[s], rows + s * MROWS, Ks[s], yb, st);
        finalize_stats_kernel<<<4, 256>>>(st, gam[s], bet[s]);
    }

    // 5) fused: acc = f4 + sum of 4 normalized+activated branches
    norm_acc4_kernel<<<n4blk, 256>>>(
        (const float4*)(ybuf + 0ull * MROWS * NOUT),
        (const float4*)(ybuf + 1ull * MROWS * NOUT),
        (const float4*)(ybuf + 2ull * MROWS * NOUT),
        (const float4*)(ybuf + 3ull * MROWS * NOUT),
        stats, (const float4*)f[4], (float4*)acc);

    // 6) final block (K=1024) + residual
    {
        float* st = stats + (size_t)4 * 2 * NOUT;
        gemm_mma_kernel<<<gemmGrid, 256>>>(acc, w[4], nullptr, 1024, ybuf, st);
        finalize_stats_kernel<<<4, 256>>>(st, gam[4], bet[4]);
        norm_final_kernel<<<n4blk, 256>>>((const float4*)ybuf, st,
                                          (const float4*)f[4],
                                          (float4*)(out + (size_t)4 * CHUNK));
    }
}

// round 4
// speedup vs baseline: 3.3837x; 1.3396x over previous
#include <cuda_runtime.h>
#include <cstdint>
#include <cstddef>

#define MROWS   8192
#define NOUT    1024
#define CHUNK   8388608
#define SLOPE   0.2f
#define EPSV    1e-5f

// ---------------------------------------------------------------------------
// Scratch
// ---------------------------------------------------------------------------
__device__ float g_ybuf[4u * MROWS * NOUT];  // branch GEMM outputs (+gemm5 reuse)
__device__ float g_abuf[7864320];            // branch A' tf32 fragment-major
__device__ float g_accf[MROWS * NOUT];       // stage-5 A' tf32 fragment-major
__device__ float g_wbuf[2031616];            // W' tf32 fragment-major (all 5)
__device__ int   g_rows[4 * MROWS];
__device__ float g_stats[5 * 2 * NOUT];      // raw [sum|sumsq] per stage

// ---------------------------------------------------------------------------
// Helpers
// ---------------------------------------------------------------------------
__device__ __forceinline__ uint32_t smem_u32(const void* p) {
    uint32_t a;
    asm("{ .reg .u64 t; cvta.to.shared.u64 t, %1; cvt.u32.u64 %0, t; }" : "=r"(a) : "l"(p));
    return a;
}
__device__ __forceinline__ float tf(float x) {
    uint32_t u;
    asm("cvt.rna.tf32.f32 %0, %1;" : "=r"(u) : "f"(x));
    return __uint_as_float(u);
}
__device__ __forceinline__ void mma_tf32(float c[4], const uint32_t a[4], const uint32_t b[2])
{
    asm volatile(
        "mma.sync.aligned.m16n8k8.row.col.f32.tf32.tf32.f32 "
        "{%0,%1,%2,%3}, {%4,%5,%6,%7}, {%8,%9}, {%0,%1,%2,%3};\n"
        : "+f"(c[0]), "+f"(c[1]), "+f"(c[2]), "+f"(c[3])
        : "r"(a[0]), "r"(a[1]), "r"(a[2]), "r"(a[3]), "r"(b[0]), "r"(b[1]));
}
__device__ __forceinline__ float leaky(float v) { return v >= 0.f ? v : SLOPE * v; }

// ---------------------------------------------------------------------------
// Index chains
// ---------------------------------------------------------------------------
__global__ void idx_kernel(const int* __restrict__ F0, const int* __restrict__ F1,
                           const int* __restrict__ F2, const int* __restrict__ F3,
                           int* __restrict__ rows)
{
    int i = blockIdx.x * blockDim.x + threadIdx.x;
    if (i >= MROWS) return;
    int b  = i >> 7;
    int i3 = F3[i];
    int i2 = F2[(b << 8) + i3];
    int i1 = F1[(b << 9) + i2];
    int i0 = F0[(b << 10) + i1];
    rows[0 * MROWS + i] = (b << 11) + i0;
    rows[1 * MROWS + i] = (b << 10) + i1;
    rows[2 * MROWS + i] = (b << 9)  + i2;
    rows[3 * MROWS + i] = (b << 8)  + i3;
}

// ---------------------------------------------------------------------------
// Pass-through copy of f0..f3 -> out slices (one launch)
// ---------------------------------------------------------------------------
__global__ void copy4_kernel(const float4* __restrict__ f0, const float4* __restrict__ f1,
                             const float4* __restrict__ f2, const float4* __restrict__ f3,
                             float4* __restrict__ out)
{
    int seg = blockIdx.y;
    size_t i = (size_t)blockIdx.x * 256 + threadIdx.x;
    const float4* src = seg == 0 ? f0 : seg == 1 ? f1 : seg == 2 ? f2 : f3;
    out[(size_t)seg * (CHUNK / 4) + i] = src[i];
}

// ---------------------------------------------------------------------------
// Gather + tf32-convert branch A operands into fragment-major layout.
// Layout (float4 index): lv = ((((mblk*nch + kc)*2 + wm)*4 + mt)*4 + kk)*32 + lane
// float4 e = { A[r(lg)][C], A[r(lg+8)][C], A[r(lg)][C+4], A[r(lg+8)][C+4] },
//   r = rows[mblk*128 + wm*64 + mt*16 + lg], C = kc*32 + kk*8 + lt.
// ---------------------------------------------------------------------------
__global__ void gatherA_kernel(const float* __restrict__ f0, const float* __restrict__ f1,
                               const float* __restrict__ f2, const float* __restrict__ f3,
                               const int* __restrict__ rows, float4* __restrict__ out)
{
    int v = blockIdx.x * 256 + threadIdx.x;   // 0 .. 1966079
    int s, base, lognch;
    if      (v < 131072) { s = 0; base = 0;      lognch = 1; }
    else if (v < 393216) { s = 1; base = 131072; lognch = 2; }
    else if (v < 917504) { s = 2; base = 393216; lognch = 3; }
    else                 { s = 3; base = 917504; lognch = 4; }
    const float* X = s == 0 ? f0 : s == 1 ? f1 : s == 2 ? f2 : f3;
    const int K = 32 << lognch;
    int lv = v - base;
    int lane = lv & 31, kk = (lv >> 5) & 3, mt = (lv >> 7) & 3, wm = (lv >> 9) & 1;
    int rest = lv >> 10;
    int kc   = rest & ((1 << lognch) - 1);
    int mblk = rest >> lognch;
    int lg = lane >> 2, lt = lane & 3;
    int gR = mblk * 128 + wm * 64 + mt * 16 + lg;
    const int* rs = rows + s * MROWS;
    int r0 = rs[gR], r1 = rs[gR + 8];
    int C = kc * 32 + kk * 8 + lt;
    float4 o;
    o.x = tf(X[(size_t)r0 * K + C]);
    o.y = tf(X[(size_t)r1 * K + C]);
    o.z = tf(X[(size_t)r0 * K + C + 4]);
    o.w = tf(X[(size_t)r1 * K + C + 4]);
    out[v] = o;
}

// ---------------------------------------------------------------------------
// Convert all 5 weight matrices into fragment-major tf32 layout.
// Layout (float4 index): lv = ((((nblk*nch + kc)*2 + wn)*8 + nt)*2 + kkp)*32 + lane
// float4 e = { W[col][k0+lt], W[col][k0+lt+4], W[col][k0+8+lt], W[col][k0+12+lt] },
//   col = nblk*128 + wn*64 + nt*8 + lg, k0 = kc*32 + kkp*16.
// ---------------------------------------------------------------------------
__global__ void convW_kernel(const float* __restrict__ w0, const float* __restrict__ w1,
                             const float* __restrict__ w2, const float* __restrict__ w3,
                             const float* __restrict__ w4, float4* __restrict__ out)
{
    int v = blockIdx.x * 256 + threadIdx.x;   // 0 .. 507903
    int s, base, lognch;
    if      (v < 16384)  { s = 0; base = 0;      lognch = 1; }
    else if (v < 49152)  { s = 1; base = 16384;  lognch = 2; }
    else if (v < 114688) { s = 2; base = 49152;  lognch = 3; }
    else if (v < 245760) { s = 3; base = 114688; lognch = 4; }
    else                 { s = 4; base = 245760; lognch = 5; }
    const float* W = s == 0 ? w0 : s == 1 ? w1 : s == 2 ? w2 : s == 3 ? w3 : w4;
    const int K = 32 << lognch;
    int lv = v - base;
    int lane = lv & 31, kkp = (lv >> 5) & 1, nt = (lv >> 6) & 7, wn = (lv >> 9) & 1;
    int rest = lv >> 10;
    int kc   = rest & ((1 << lognch) - 1);
    int nblk = rest >> lognch;
    int lg = lane >> 2, lt = lane & 3;
    int col = nblk * 128 + wn * 64 + nt * 8 + lg;
    const float* wr = W + (size_t)col * K + kc * 32 + kkp * 16;
    float4 o;
    o.x = tf(wr[lt]);
    o.y = tf(wr[lt + 4]);
    o.z = tf(wr[lt + 8]);
    o.w = tf(wr[lt + 12]);
    out[v] = o;
}

// ---------------------------------------------------------------------------
// Pipelined tf32 tensor-core GEMM on pre-converted fragment-major operands.
//   Y[m,n] = sum_k A[m,k] * W[n,k]   (+ fused per-column BN raw stats)
// CTA 128x128, 4 warps (2m x 2n of 64x64), BK=32, 3-stage cp.async pipeline.
// ---------------------------------------------------------------------------
__global__ __launch_bounds__(128, 2) void gemm_mma_kernel(
    const float* __restrict__ A, const float* __restrict__ B,
    int nch, float* __restrict__ Y, float* __restrict__ st)
{
    extern __shared__ float smbuf[];   // 3 stages x (4096 A + 4096 B) floats
    const int tid = threadIdx.x, lane = tid & 31, wid = tid >> 5;
    const int wm = wid & 1, wn = wid >> 1;
    const int bn = blockIdx.x, bm = blockIdx.y;
    const int lg = lane >> 2, lt = lane & 3;
    const float* Ag = A + (size_t)bm * nch * 4096;
    const float* Bg = B + (size_t)bn * nch * 4096;
    const uint32_t sb = smem_u32(smbuf);

    float c[4][8][4];
#pragma unroll
    for (int mt = 0; mt < 4; mt++)
#pragma unroll
        for (int nt = 0; nt < 8; nt++)
#pragma unroll
            for (int j = 0; j < 4; j++) c[mt][nt][j] = 0.f;

    // prologue: prefetch up to 2 chunks
    int fetch = 0;
#pragma unroll
    for (int p = 0; p < 2; p++) {
        if (fetch < nch) {
            const float* as = Ag + (size_t)fetch * 4096 + tid * 4;
            const float* bs = Bg + (size_t)fetch * 4096 + tid * 4;
            uint32_t da = sb + (uint32_t)(p * 8192 + tid * 4) * 4;
            uint32_t db = da + 16384;
#pragma unroll
            for (int i = 0; i < 8; i++) {
                asm volatile("cp.async.cg.shared.global [%0], [%1], 16;" :: "r"(da + i * 2048), "l"(as + i * 512));
                asm volatile("cp.async.cg.shared.global [%0], [%1], 16;" :: "r"(db + i * 2048), "l"(bs + i * 512));
            }
        }
        asm volatile("cp.async.commit_group;");
        fetch++;
    }

    int cs = 0, fs = 2;
    for (int ch = 0; ch < nch; ch++) {
        asm volatile("cp.async.wait_group 1;");
        __syncthreads();
        const float* As = smbuf + cs * 8192;
        const float* Bs = As + 4096;
#pragma unroll
        for (int kkp = 0; kkp < 2; kkp++) {
            float4 bv[8];
#pragma unroll
            for (int nt = 0; nt < 8; nt++)
                bv[nt] = *(const float4*)(Bs + (((wn * 8 + nt) * 2 + kkp) * 128) + lane * 4);
#pragma unroll
            for (int j = 0; j < 2; j++) {
                const int kk = kkp * 2 + j;
                float4 av[4];
#pragma unroll
                for (int mt = 0; mt < 4; mt++)
                    av[mt] = *(const float4*)(As + (((wm * 4 + mt) * 4 + kk) * 128) + lane * 4);
#pragma unroll
                for (int mt = 0; mt < 4; mt++) {
                    uint32_t a[4] = { __float_as_uint(av[mt].x), __float_as_uint(av[mt].y),
                                      __float_as_uint(av[mt].z), __float_as_uint(av[mt].w) };
#pragma unroll
                    for (int nt = 0; nt < 8; nt++) {
                        uint32_t b[2];
                        b[0] = __float_as_uint(j ? bv[nt].z : bv[nt].x);
                        b[1] = __float_as_uint(j ? bv[nt].w : bv[nt].y);
                        mma_tf32(c[mt][nt], a, b);
                    }
                }
            }
        }
        if (fetch < nch) {
            const float* as = Ag + (size_t)fetch * 4096 + tid * 4;
            const float* bs = Bg + (size_t)fetch * 4096 + tid * 4;
            uint32_t da = sb + (uint32_t)(fs * 8192 + tid * 4) * 4;
            uint32_t db = da + 16384;
#pragma unroll
            for (int i = 0; i < 8; i++) {
                asm volatile("cp.async.cg.shared.global [%0], [%1], 16;" :: "r"(da + i * 2048), "l"(as + i * 512));
                asm volatile("cp.async.cg.shared.global [%0], [%1], 16;" :: "r"(db + i * 2048), "l"(bs + i * 512));
            }
        }
        asm volatile("cp.async.commit_group;");
        fetch++;
        if (++cs == 3) cs = 0;
        if (++fs == 3) fs = 0;
    }

    // Epilogue: Y stores + fused BN raw stats.
    const int rowbase = bm * 128 + wm * 64 + lg;
    const int colbase = bn * 128 + wn * 64 + lt * 2;
#pragma unroll
    for (int mt = 0; mt < 4; mt++) {
        const int r0 = rowbase + mt * 16;
#pragma unroll
        for (int nt = 0; nt < 8; nt++) {
            const int cc = colbase + nt * 8;
            *(float2*)&Y[(size_t)r0 * NOUT + cc]       = make_float2(c[mt][nt][0], c[mt][nt][1]);
            *(float2*)&Y[(size_t)(r0 + 8) * NOUT + cc] = make_float2(c[mt][nt][2], c[mt][nt][3]);
        }
    }
#pragma unroll
    for (int nt = 0; nt < 8; nt++) {
        float s0 = 0.f, s1 = 0.f, q0 = 0.f, q1 = 0.f;
#pragma unroll
        for (int mt = 0; mt < 4; mt++) {
            float e0 = c[mt][nt][0], e1 = c[mt][nt][1];
            float e2 = c[mt][nt][2], e3 = c[mt][nt][3];
            s0 += e0 + e2; s1 += e1 + e3;
            q0 += e0 * e0 + e2 * e2;
            q1 += e1 * e1 + e3 * e3;
        }
#pragma unroll
        for (int off = 4; off < 32; off <<= 1) {
            s0 += __shfl_xor_sync(0xffffffffu, s0, off);
            s1 += __shfl_xor_sync(0xffffffffu, s1, off);
            q0 += __shfl_xor_sync(0xffffffffu, q0, off);
            q1 += __shfl_xor_sync(0xffffffffu, q1, off);
        }
        if (lane < 4) {
            int col = bn * 128 + wn * 64 + nt * 8 + lane * 2;
            atomicAdd(&st[col],            s0);
            atomicAdd(&st[col + 1],        s1);
            atomicAdd(&st[NOUT + col],     q0);
            atomicAdd(&st[NOUT + col + 1], q1);
        }
    }
}

// ---------------------------------------------------------------------------
// Fused: finalize BN for stages 0-3 + acc = f4 + sum leaky(norm(y_s)),
// written directly as stage-5 fragment-major tf32 A operand.
// Grid: 64 mblk x 32 kc. Block 256.
// ---------------------------------------------------------------------------
__global__ __launch_bounds__(256) void norm_acc4_kernel(
    const float* __restrict__ y0, const float* __restrict__ y1,
    const float* __restrict__ y2, const float* __restrict__ y3,
    const float* __restrict__ f4,
    const float* __restrict__ stats,
    const float* __restrict__ g0, const float* __restrict__ g1,
    const float* __restrict__ g2, const float* __restrict__ g3,
    const float* __restrict__ be0, const float* __restrict__ be1,
    const float* __restrict__ be2, const float* __restrict__ be3,
    float4* __restrict__ accf)
{
    __shared__ float sm[128 * 36];
    __shared__ float scsh[4][2][32];
    const int mblk = blockIdx.x >> 5;
    const int kc   = blockIdx.x & 31;
    const int tid  = threadIdx.x;

    if (tid < 128) {
        int s = tid >> 5, lc = tid & 31;
        const float* st = stats + s * 2048;
        int ch = kc * 32 + lc;
        const float* gp  = s == 0 ? g0  : s == 1 ? g1  : s == 2 ? g2  : g3;
        const float* bep = s == 0 ? be0 : s == 1 ? be1 : s == 2 ? be2 : be3;
        const float inv = 1.0f / (float)MROWS;
        float mean = st[ch] * inv;
        float var  = st[NOUT + ch] * inv - mean * mean;
        float sc   = rsqrtf(var + EPSV) * gp[ch];
        scsh[s][0][lc] = sc;
        scsh[s][1][lc] = bep[ch] - mean * sc;
    }
    __syncthreads();

    const float* ys[4] = {y0, y1, y2, y3};
#pragma unroll
    for (int i = 0; i < 4; i++) {
        int v = tid + 256 * i;          // 0..1023 float4s of the 128x32 chunk
        int r = v >> 3, cq = (v & 7) * 4;
        size_t off = ((size_t)(mblk * 128 + r)) * NOUT + kc * 32 + cq;
        float4 a = *(const float4*)(f4 + off);
#pragma unroll
        for (int s = 0; s < 4; s++) {
            float4 y = *(const float4*)(ys[s] + off);
            a.x += leaky(y.x * scsh[s][0][cq + 0] + scsh[s][1][cq + 0]);
            a.y += leaky(y.y * scsh[s][0][cq + 1] + scsh[s][1][cq + 1]);
            a.z += leaky(y.z * scsh[s][0][cq + 2] + scsh[s][1][cq + 2]);
            a.w += leaky(y.w * scsh[s][0][cq + 3] + scsh[s][1][cq + 3]);
        }
        *(float4*)&sm[r * 36 + cq] = a;
    }
    __syncthreads();

#pragma unroll
    for (int i = 0; i < 4; i++) {
        int o = tid + 256 * i;          // fragment-major float4 index in chunk
        int lane = o & 31, kk = (o >> 5) & 3, mt = (o >> 7) & 3, wm = (o >> 9) & 1;
        int lg = lane >> 2, lt = lane & 3;
        int r0 = wm * 64 + mt * 16 + lg;
        int C  = kk * 8 + lt;
        float4 w;
        w.x = tf(sm[r0 * 36 + C]);
        w.y = tf(sm[(r0 + 8) * 36 + C]);
        w.z = tf(sm[r0 * 36 + C + 4]);
        w.w = tf(sm[(r0 + 8) * 36 + C + 4]);
        accf[((size_t)(mblk * 32 + kc)) * 1024 + o] = w;
    }
}

// ---------------------------------------------------------------------------
// Finalize stage-4 stats into scale/shift (in place)
// ---------------------------------------------------------------------------
__global__ void finalize_stats_kernel(float* __restrict__ st,
                                      const float* __restrict__ g,
                                      const float* __restrict__ be)
{
    int c = blockIdx.x * blockDim.x + threadIdx.x;
    if (c >= NOUT) return;
    const float inv = 1.0f / (float)MROWS;
    float mean = st[c] * inv;
    float var  = st[NOUT + c] * inv - mean * mean;
    float sc   = rsqrtf(var + EPSV) * g[c];
    st[c]        = sc;
    st[NOUT + c] = be[c] - mean * sc;
}

// out = leaky(y * sc + sh) + f4
__global__ void norm_final_kernel(const float4* __restrict__ Y,
                                  const float* __restrict__ st,
                                  const float4* __restrict__ f4,
                                  float4* __restrict__ out)
{
    int i = blockIdx.x * blockDim.x + threadIdx.x;
    int c4 = i & 255;
    float4 sc = ((const float4*)st)[c4];
    float4 sh = ((const float4*)(st + NOUT))[c4];
    float4 y = Y[i];
    float4 r = f4[i];
    float4 o;
    o.x = leaky(y.x * sc.x + sh.x) + r.x;
    o.y = leaky(y.y * sc.y + sh.y) + r.y;
    o.z = leaky(y.z * sc.z + sh.z) + r.z;
    o.w = leaky(y.w * sc.w + sh.w) + r.w;
    out[i] = o;
}

// ---------------------------------------------------------------------------
// Host launcher
// ---------------------------------------------------------------------------
extern "C" void kernel_launch(void* const* d_in, const int* in_sizes, int n_in,
                              void* d_out, int out_size)
{
    (void)in_sizes; (void)n_in; (void)out_size;

    const float* f[5];
    for (int i = 0; i < 5; i++) f[i] = (const float*)d_in[1 + i];
    const int* FPS[4];
    for (int i = 0; i < 4; i++) FPS[i] = (const int*)d_in[6 + i];

    const float* w[5]; const float* gam[5]; const float* bet[5];
    for (int i = 0; i < 5; i++) {
        w[i]   = (const float*)d_in[10 + 4 * i + 0];
        gam[i] = (const float*)d_in[10 + 4 * i + 2];
        bet[i] = (const float*)d_in[10 + 4 * i + 3];
    }

    float* out = (float*)d_out;

    float *ybuf, *abuf, *accf, *wbuf, *stats;
    int   *rows;
    cudaGetSymbolAddress((void**)&ybuf,  g_ybuf);
    cudaGetSymbolAddress((void**)&abuf,  g_abuf);
    cudaGetSymbolAddress((void**)&accf,  g_accf);
    cudaGetSymbolAddress((void**)&wbuf,  g_wbuf);
    cudaGetSymbolAddress((void**)&stats, g_stats);
    cudaGetSymbolAddress((void**)&rows,  g_rows);

    cudaFuncSetAttribute(gemm_mma_kernel,
                         cudaFuncAttributeMaxDynamicSharedMemorySize, 98304);

    // pass-through copies (one launch)
    copy4_kernel<<<dim3(CHUNK / 4 / 256, 4), 256>>>(
        (const float4*)f[0], (const float4*)f[1],
        (const float4*)f[2], (const float4*)f[3], (float4*)out);

    cudaMemsetAsync(stats, 0, 5 * 2 * NOUT * sizeof(float), 0);

    idx_kernel<<<MROWS / 256, 256>>>(FPS[0], FPS[1], FPS[2], FPS[3], rows);

    gatherA_kernel<<<7680, 256>>>(f[0], f[1], f[2], f[3], rows, (float4*)abuf);
    convW_kernel<<<1984, 256>>>(w[0], w[1], w[2], w[3], w[4], (float4*)wbuf);

    const size_t aoff[4] = {0, 524288, 1572864, 3670016};
    const size_t woff[5] = {0, 65536, 196608, 458752, 983040};
    const int    nchs[5] = {2, 4, 8, 16, 32};
    dim3 gemmGrid(8, 64);

    for (int s = 0; s < 4; s++) {
        gemm_mma_kernel<<<gemmGrid, 128, 98304>>>(
            abuf + aoff[s], wbuf + woff[s], nchs[s],
            ybuf + (size_t)s * MROWS * NOUT, stats + (size_t)s * 2048);
    }

    norm_acc4_kernel<<<2048, 256>>>(
        ybuf + 0ull * MROWS * NOUT, ybuf + 1ull * MROWS * NOUT,
        ybuf + 2ull * MROWS * NOUT, ybuf + 3ull * MROWS * NOUT,
        f[4], stats,
        gam[0], gam[1], gam[2], gam[3],
        bet[0], bet[1], bet[2], bet[3],
        (float4*)accf);

    gemm_mma_kernel<<<gemmGrid, 128, 98304>>>(
        accf, wbuf + woff[4], nchs[4], ybuf, stats + 4 * 2048);

    finalize_stats_kernel<<<4, 256>>>(stats + 4 * 2048, gam[4], bet[4]);

    norm_final_kernel<<<CHUNK / 4 / 256, 256>>>(
        (const float4*)ybuf, stats + 4 * 2048,
        (const float4*)f[4], (float4*)(out + (size_t)4 * CHUNK));
}

// round 6
// speedup vs baseline: 4.6801x; 1.3831x over previous
#include <cuda_runtime.h>
#include <cuda_fp16.h>
#include <cstdint>
#include <cstddef>

#define MROWS   8192
#define NOUT    1024
#define CHUNK   8388608
#define SLOPE   0.2f
#define EPSV    1e-5f

// ---------------------------------------------------------------------------
// Scratch (device globals)
// ---------------------------------------------------------------------------
__device__ float g_ybuf[4u * MROWS * NOUT];  // branch GEMM outputs (+gemm5 reuse)
__device__ uint4 g_abuf[983040];             // branch A' fp16 fragment-major
__device__ uint4 g_accf[1048576];            // stage-5 A' fp16 fragment-major (16MB)
__device__ uint4 g_wbuf[253952];             // W' fp16 fragment-major (all 5)
__device__ int   g_rows[4 * MROWS];
__device__ float g_stats[5 * 2 * NOUT];      // raw [sum|sumsq] per stage

// Cached side-stream/events (infra only; captured work is identical per call)
static cudaStream_t g_s2 = nullptr;
static cudaEvent_t  g_e1 = nullptr, g_e2 = nullptr;

// ---------------------------------------------------------------------------
// Helpers
// ---------------------------------------------------------------------------
__device__ __forceinline__ uint32_t smem_u32(const void* p) {
    uint32_t a;
    asm("{ .reg .u64 t; cvta.to.shared.u64 t, %1; cvt.u32.u64 %0, t; }" : "=r"(a) : "l"(p));
    return a;
}
__device__ __forceinline__ uint32_t h2pack(float a, float b) {
    __half2 h = __floats2half2_rn(a, b);
    return *(uint32_t*)&h;
}
__device__ __forceinline__ void mma_f16(float c[4], const uint4& a, uint32_t b0, uint32_t b1)
{
    asm volatile(
        "mma.sync.aligned.m16n8k16.row.col.f32.f16.f16.f32 "
        "{%0,%1,%2,%3}, {%4,%5,%6,%7}, {%8,%9}, {%0,%1,%2,%3};\n"
        : "+f"(c[0]), "+f"(c[1]), "+f"(c[2]), "+f"(c[3])
        : "r"(a.x), "r"(a.y), "r"(a.z), "r"(a.w), "r"(b0), "r"(b1));
}
__device__ __forceinline__ float leaky(float v) { return v >= 0.f ? v : SLOPE * v; }

// ---------------------------------------------------------------------------
// Index chains
// ---------------------------------------------------------------------------
__global__ void idx_kernel(const int* __restrict__ F0, const int* __restrict__ F1,
                           const int* __restrict__ F2, const int* __restrict__ F3,
                           int* __restrict__ rows)
{
    int i = blockIdx.x * blockDim.x + threadIdx.x;
    if (i >= MROWS) return;
    int b  = i >> 7;
    int i3 = F3[i];
    int i2 = F2[(b << 8) + i3];
    int i1 = F1[(b << 9) + i2];
    int i0 = F0[(b << 10) + i1];
    rows[0 * MROWS + i] = (b << 11) + i0;
    rows[1 * MROWS + i] = (b << 10) + i1;
    rows[2 * MROWS + i] = (b << 9)  + i2;
    rows[3 * MROWS + i] = (b << 8)  + i3;
}

// ---------------------------------------------------------------------------
// Pass-through copy of f0..f3 -> out slices (runs on a forked stream)
// ---------------------------------------------------------------------------
__global__ void copy4_kernel(const float4* __restrict__ f0, const float4* __restrict__ f1,
                             const float4* __restrict__ f2, const float4* __restrict__ f3,
                             float4* __restrict__ out)
{
    int seg = blockIdx.y;
    size_t i = (size_t)blockIdx.x * 256 + threadIdx.x;
    const float4* src = seg == 0 ? f0 : seg == 1 ? f1 : seg == 2 ? f2 : f3;
    out[(size_t)seg * (CHUNK / 4) + i] = src[i];
}

// ---------------------------------------------------------------------------
// Gather + fp16-convert branch A operands into m16n8k16 fragment-major layout.
// uint4 index: base_s + (mblk*nch + kc)*512 + wm*256 + (mt*2+ks)*32 + lane
// regs: {A[r0][c0..c0+1], A[r1][c0..+1], A[r0][c0+8..+9], A[r1][c0+8..+9]},
//   r0 = rows[mblk*128+wm*64+mt*16+lg], r1 = row+8, c0 = kc*32+ks*16+2lt.
// ---------------------------------------------------------------------------
__global__ void gatherA_kernel(const float* __restrict__ f0, const float* __restrict__ f1,
                               const float* __restrict__ f2, const float* __restrict__ f3,
                               const int* __restrict__ rows, uint4* __restrict__ out)
{
    int v = blockIdx.x * 256 + threadIdx.x;   // 0 .. 983039
    int s, base, lognch;
    if      (v < 65536)  { s = 0; base = 0;      lognch = 1; }
    else if (v < 196608) { s = 1; base = 65536;  lognch = 2; }
    else if (v < 458752) { s = 2; base = 196608; lognch = 3; }
    else                 { s = 3; base = 458752; lognch = 4; }
    const float* X = s == 0 ? f0 : s == 1 ? f1 : s == 2 ? f2 : f3;
    const int K = 32 << lognch;
    int lv = v - base;
    int lane = lv & 31, f = (lv >> 5) & 7, wm = (lv >> 8) & 1;
    int mt = f >> 1, ks = f & 1;
    int rest = lv >> 9;
    int kc   = rest & ((1 << lognch) - 1);
    int mblk = rest >> lognch;
    int lg = lane >> 2, lt = lane & 3;
    int gR = mblk * 128 + wm * 64 + mt * 16 + lg;
    const int* rs = rows + s * MROWS;
    int r0 = rs[gR], r1 = rs[gR + 8];
    int c0 = kc * 32 + ks * 16 + lt * 2;
    const float* p0 = X + (size_t)r0 * K + c0;
    const float* p1 = X + (size_t)r1 * K + c0;
    float2 a0 = *(const float2*)p0,       a1 = *(const float2*)p1;
    float2 a2 = *(const float2*)(p0 + 8), a3 = *(const float2*)(p1 + 8);
    uint4 o;
    o.x = h2pack(a0.x, a0.y);
    o.y = h2pack(a1.x, a1.y);
    o.z = h2pack(a2.x, a2.y);
    o.w = h2pack(a3.x, a3.y);
    out[v] = o;
}

// ---------------------------------------------------------------------------
// Convert all 5 weight matrices into fp16 fragment-major B layout.
// uint4 index: base_s + (nblk*nch + kc)*512 + wn*256 + nt*32 + lane
// regs: ks0{W[col][k0+2lt..+1], W[col][k0+2lt+8..+9]}, ks1 same at k0+16.
// ---------------------------------------------------------------------------
__global__ void convW_kernel(const float* __restrict__ w0, const float* __restrict__ w1,
                             const float* __restrict__ w2, const float* __restrict__ w3,
                             const float* __restrict__ w4, uint4* __restrict__ out)
{
    int v = blockIdx.x * 256 + threadIdx.x;   // 0 .. 253951
    int s, base, lognch;
    if      (v < 8192)   { s = 0; base = 0;      lognch = 1; }
    else if (v < 24576)  { s = 1; base = 8192;   lognch = 2; }
    else if (v < 57344)  { s = 2; base = 24576;  lognch = 3; }
    else if (v < 122880) { s = 3; base = 57344;  lognch = 4; }
    else                 { s = 4; base = 122880; lognch = 5; }
    const float* W = s == 0 ? w0 : s == 1 ? w1 : s == 2 ? w2 : s == 3 ? w3 : w4;
    const int K = 32 << lognch;
    int lv = v - base;
    int lane = lv & 31, nt = (lv >> 5) & 7, wn = (lv >> 8) & 1;
    int rest = lv >> 9;
    int kc   = rest & ((1 << lognch) - 1);
    int nblk = rest >> lognch;
    int lg = lane >> 2, lt = lane & 3;
    int col = nblk * 128 + wn * 64 + nt * 8 + lg;
    const float* wr = W + (size_t)col * K + kc * 32 + lt * 2;
    float2 b0 = *(const float2*)wr;
    float2 b1 = *(const float2*)(wr + 8);
    float2 b2 = *(const float2*)(wr + 16);
    float2 b3 = *(const float2*)(wr + 24);
    uint4 o;
    o.x = h2pack(b0.x, b0.y);
    o.y = h2pack(b1.x, b1.y);
    o.z = h2pack(b2.x, b2.y);
    o.w = h2pack(b3.x, b3.y);
    out[v] = o;
}

// ---------------------------------------------------------------------------
// Pipelined fp16 tensor-core GEMM on fragment-major operands.
//   Y[m,n] = sum_k A[m,k] * W[n,k]   (+ fused per-column BN raw stats)
// CTA 128x128, 4 warps (2m x 2n of 64x64), BK=32, 3-stage cp.async pipeline.
// Per chunk per CTA: 512 uint4 A + 512 uint4 B = 16 KB.
// ---------------------------------------------------------------------------
__global__ __launch_bounds__(128, 2) void gemm_mma_kernel(
    const uint4* __restrict__ A, const uint4* __restrict__ B,
    int nch, float* __restrict__ Y, float* __restrict__ st)
{
    __shared__ uint4 sm[3][1024];   // per stage: A[0:512), B[512:1024)
    const int tid = threadIdx.x, lane = tid & 31, wid = tid >> 5;
    const int wm = wid & 1, wn = wid >> 1;
    const int bn = blockIdx.x, bm = blockIdx.y;
    const int lg = lane >> 2, lt = lane & 3;
    const uint4* Ag = A + (size_t)bm * nch * 512;
    const uint4* Bg = B + (size_t)bn * nch * 512;
    const uint32_t sb = smem_u32(sm);

    float c[4][8][4];
#pragma unroll
    for (int mt = 0; mt < 4; mt++)
#pragma unroll
        for (int nt = 0; nt < 8; nt++)
#pragma unroll
            for (int j = 0; j < 4; j++) c[mt][nt][j] = 0.f;

    int fetch = 0;
#pragma unroll
    for (int p = 0; p < 2; p++) {
        if (fetch < nch) {
            const uint4* as = Ag + (size_t)fetch * 512 + tid;
            const uint4* bs = Bg + (size_t)fetch * 512 + tid;
            uint32_t da = sb + (uint32_t)(p * 1024 + tid) * 16;
#pragma unroll
            for (int i = 0; i < 4; i++) {
                asm volatile("cp.async.cg.shared.global [%0], [%1], 16;" :: "r"(da + i * 2048), "l"(as + i * 128));
                asm volatile("cp.async.cg.shared.global [%0], [%1], 16;" :: "r"(da + 8192 + i * 2048), "l"(bs + i * 128));
            }
        }
        asm volatile("cp.async.commit_group;");
        fetch++;
    }

    int cs = 0, fs = 2;
    for (int ch = 0; ch < nch; ch++) {
        asm volatile("cp.async.wait_group 1;");
        __syncthreads();
        const uint4* As = sm[cs];
        const uint4* Bs = sm[cs] + 512;

        uint4 aq[8], bq[8];
#pragma unroll
        for (int f = 0; f < 8; f++) aq[f] = As[(wm * 8 + f) * 32 + lane];
#pragma unroll
        for (int nt = 0; nt < 8; nt++) bq[nt] = Bs[(wn * 8 + nt) * 32 + lane];

#pragma unroll
        for (int ks = 0; ks < 2; ks++)
#pragma unroll
            for (int mt = 0; mt < 4; mt++) {
                const uint4& a = aq[mt * 2 + ks];
#pragma unroll
                for (int nt = 0; nt < 8; nt++) {
                    uint32_t b0 = ks ? bq[nt].z : bq[nt].x;
                    uint32_t b1 = ks ? bq[nt].w : bq[nt].y;
                    mma_f16(c[mt][nt], a, b0, b1);
                }
            }

        if (fetch < nch) {
            const uint4* as = Ag + (size_t)fetch * 512 + tid;
            const uint4* bs = Bg + (size_t)fetch * 512 + tid;
            uint32_t da = sb + (uint32_t)(fs * 1024 + tid) * 16;
#pragma unroll
            for (int i = 0; i < 4; i++) {
                asm volatile("cp.async.cg.shared.global [%0], [%1], 16;" :: "r"(da + i * 2048), "l"(as + i * 128));
                asm volatile("cp.async.cg.shared.global [%0], [%1], 16;" :: "r"(da + 8192 + i * 2048), "l"(bs + i * 128));
            }
        }
        asm volatile("cp.async.commit_group;");
        fetch++;
        if (++cs == 3) cs = 0;
        if (++fs == 3) fs = 0;
    }

    // Epilogue: Y stores + fused BN raw stats.
    const int rowbase = bm * 128 + wm * 64 + lg;
    const int colbase = bn * 128 + wn * 64 + lt * 2;
#pragma unroll
    for (int mt = 0; mt < 4; mt++) {
        const int r0 = rowbase + mt * 16;
#pragma unroll
        for (int nt = 0; nt < 8; nt++) {
            const int cc = colbase + nt * 8;
            *(float2*)&Y[(size_t)r0 * NOUT + cc]       = make_float2(c[mt][nt][0], c[mt][nt][1]);
            *(float2*)&Y[(size_t)(r0 + 8) * NOUT + cc] = make_float2(c[mt][nt][2], c[mt][nt][3]);
        }
    }
#pragma unroll
    for (int nt = 0; nt < 8; nt++) {
        float s0 = 0.f, s1 = 0.f, q0 = 0.f, q1 = 0.f;
#pragma unroll
        for (int mt = 0; mt < 4; mt++) {
            float e0 = c[mt][nt][0], e1 = c[mt][nt][1];
            float e2 = c[mt][nt][2], e3 = c[mt][nt][3];
            s0 += e0 + e2; s1 += e1 + e3;
            q0 += e0 * e0 + e2 * e2;
            q1 += e1 * e1 + e3 * e3;
        }
#pragma unroll
        for (int off = 4; off < 32; off <<= 1) {
            s0 += __shfl_xor_sync(0xffffffffu, s0, off);
            s1 += __shfl_xor_sync(0xffffffffu, s1, off);
            q0 += __shfl_xor_sync(0xffffffffu, q0, off);
            q1 += __shfl_xor_sync(0xffffffffu, q1, off);
        }
        if (lane < 4) {
            int col = bn * 128 + wn * 64 + nt * 8 + lane * 2;
            atomicAdd(&st[col],            s0);
            atomicAdd(&st[col + 1],        s1);
            atomicAdd(&st[NOUT + col],     q0);
            atomicAdd(&st[NOUT + col + 1], q1);
        }
    }
}

// ---------------------------------------------------------------------------
// Fused: finalize BN for stages 0-3 + acc = f4 + sum leaky(norm(y_s)),
// written directly as stage-5 fp16 fragment-major A operand.
// Grid: 2048 = 64 mblk x 32 kc. Block 256.
// ---------------------------------------------------------------------------
__global__ __launch_bounds__(256) void norm_acc4_kernel(
    const float* __restrict__ y0, const float* __restrict__ y1,
    const float* __restrict__ y2, const float* __restrict__ y3,
    const float* __restrict__ f4,
    const float* __restrict__ stats,
    const float* __restrict__ g0, const float* __restrict__ g1,
    const float* __restrict__ g2, const float* __restrict__ g3,
    const float* __restrict__ be0, const float* __restrict__ be1,
    const float* __restrict__ be2, const float* __restrict__ be3,
    uint4* __restrict__ accf)
{
    __shared__ float smt[128 * 36];
    __shared__ float scsh[4][2][32];
    const int mblk = blockIdx.x >> 5;
    const int kc   = blockIdx.x & 31;
    const int tid  = threadIdx.x;

    if (tid < 128) {
        int s = tid >> 5, lc = tid & 31;
        const float* st = stats + s * 2048;
        int ch = kc * 32 + lc;
        const float* gp  = s == 0 ? g0  : s == 1 ? g1  : s == 2 ? g2  : g3;
        const float* bep = s == 0 ? be0 : s == 1 ? be1 : s == 2 ? be2 : be3;
        const float inv = 1.0f / (float)MROWS;
        float mean = st[ch] * inv;
        float var  = st[NOUT + ch] * inv - mean * mean;
        float sc   = rsqrtf(var + EPSV) * gp[ch];
        scsh[s][0][lc] = sc;
        scsh[s][1][lc] = bep[ch] - mean * sc;
    }
    __syncthreads();

    const float* ys[4] = {y0, y1, y2, y3};
#pragma unroll
    for (int i = 0; i < 4; i++) {
        int v = tid + 256 * i;          // 0..1023 float4s of the 128x32 chunk
        int r = v >> 3, cq = (v & 7) * 4;
        size_t off = ((size_t)(mblk * 128 + r)) * NOUT + kc * 32 + cq;
        float4 a = *(const float4*)(f4 + off);
#pragma unroll
        for (int s = 0; s < 4; s++) {
            float4 y = *(const float4*)(ys[s] + off);
            a.x += leaky(y.x * scsh[s][0][cq + 0] + scsh[s][1][cq + 0]);
            a.y += leaky(y.y * scsh[s][0][cq + 1] + scsh[s][1][cq + 1]);
            a.z += leaky(y.z * scsh[s][0][cq + 2] + scsh[s][1][cq + 2]);
            a.w += leaky(y.w * scsh[s][0][cq + 3] + scsh[s][1][cq + 3]);
        }
        *(float4*)&smt[r * 36 + cq] = a;
    }
    __syncthreads();

#pragma unroll
    for (int i = 0; i < 2; i++) {
        int o = tid + 256 * i;          // 0..511 fragment uint4 in this chunk
        int lane = o & 31, f = (o >> 5) & 7, wm = (o >> 8) & 1;
        int mt = f >> 1, ks = f & 1;
        int lg = lane >> 2, lt = lane & 3;
        int r0 = wm * 64 + mt * 16 + lg;
        int c0 = ks * 16 + lt * 2;
        uint4 w;
        w.x = h2pack(smt[r0 * 36 + c0],       smt[r0 * 36 + c0 + 1]);
        w.y = h2pack(smt[(r0 + 8) * 36 + c0], smt[(r0 + 8) * 36 + c0 + 1]);
        w.z = h2pack(smt[r0 * 36 + c0 + 8],       smt[r0 * 36 + c0 + 9]);
        w.w = h2pack(smt[(r0 + 8) * 36 + c0 + 8], smt[(r0 + 8) * 36 + c0 + 9]);
        accf[((size_t)(mblk * 32 + kc)) * 512 + o] = w;
    }
}

// ---------------------------------------------------------------------------
// Finalize stage-4 stats into scale/shift (in place)
// ---------------------------------------------------------------------------
__global__ void finalize_stats_kernel(float* __restrict__ st,
                                      const float* __restrict__ g,
                                      const float* __restrict__ be)
{
    int c = blockIdx.x * blockDim.x + threadIdx.x;
    if (c >= NOUT) return;
    const float inv = 1.0f / (float)MROWS;
    float mean = st[c] * inv;
    float var  = st[NOUT + c] * inv - mean * mean;
    float sc   = rsqrtf(var + EPSV) * g[c];
    st[c]        = sc;
    st[NOUT + c] = be[c] - mean * sc;
}

// out = leaky(y * sc + sh) + f4
__global__ void norm_final_kernel(const float4* __restrict__ Y,
                                  const float* __restrict__ st,
                                  const float4* __restrict__ f4,
                                  float4* __restrict__ out)
{
    int i = blockIdx.x * blockDim.x + threadIdx.x;
    int c4 = i & 255;
    float4 sc = ((const float4*)st)[c4];
    float4 sh = ((const float4*)(st + NOUT))[c4];
    float4 y = Y[i];
    float4 r = f4[i];
    float4 o;
    o.x = leaky(y.x * sc.x + sh.x) + r.x;
    o.y = leaky(y.y * sc.y + sh.y) + r.y;
    o.z = leaky(y.z * sc.z + sh.z) + r.z;
    o.w = leaky(y.w * sc.w + sh.w) + r.w;
    out[i] = o;
}

// ---------------------------------------------------------------------------
// Host launcher
// ---------------------------------------------------------------------------
extern "C" void kernel_launch(void* const* d_in, const int* in_sizes, int n_in,
                              void* d_out, int out_size)
{
    (void)in_sizes; (void)n_in; (void)out_size;

    const float* f[5];
    for (int i = 0; i < 5; i++) f[i] = (const float*)d_in[1 + i];
    const int* FPS[4];
    for (int i = 0; i < 4; i++) FPS[i] = (const int*)d_in[6 + i];

    const float* w[5]; const float* gam[5]; const float* bet[5];
    for (int i = 0; i < 5; i++) {
        w[i]   = (const float*)d_in[10 + 4 * i + 0];
        gam[i] = (const float*)d_in[10 + 4 * i + 2];
        bet[i] = (const float*)d_in[10 + 4 * i + 3];
    }

    float* out = (float*)d_out;

    float *ybuf, *stats;
    uint4 *abuf, *accf, *wbuf;
    int   *rows;
    cudaGetSymbolAddress((void**)&ybuf,  g_ybuf);
    cudaGetSymbolAddress((void**)&abuf,  g_abuf);
    cudaGetSymbolAddress((void**)&accf,  g_accf);
    cudaGetSymbolAddress((void**)&wbuf,  g_wbuf);
    cudaGetSymbolAddress((void**)&stats, g_stats);
    cudaGetSymbolAddress((void**)&rows,  g_rows);

    // One-time side-stream for overlapping the pass-through copy with compute.
    if (!g_s2) {
        cudaStreamCreateWithFlags(&g_s2, cudaStreamNonBlocking);
        cudaEventCreateWithFlags(&g_e1, cudaEventDisableTiming);
        cudaEventCreateWithFlags(&g_e2, cudaEventDisableTiming);
    }

    // Fork: pass-through copies on side stream, concurrent with compute chain.
    cudaEventRecord(g_e1, 0);
    cudaStreamWaitEvent(g_s2, g_e1, 0);
    copy4_kernel<<<dim3(CHUNK / 4 / 256, 4), 256, 0, g_s2>>>(
        (const float4*)f[0], (const float4*)f[1],
        (const float4*)f[2], (const float4*)f[3], (float4*)out);
    cudaEventRecord(g_e2, g_s2);

    // Main chain (default stream)
    cudaMemsetAsync(stats, 0, 5 * 2 * NOUT * sizeof(float), 0);
    idx_kernel<<<MROWS / 256, 256>>>(FPS[0], FPS[1], FPS[2], FPS[3], rows);
    gatherA_kernel<<<3840, 256>>>(f[0], f[1], f[2], f[3], rows, abuf);
    convW_kernel<<<992, 256>>>(w[0], w[1], w[2], w[3], w[4], wbuf);

    const size_t aoff[4] = {0, 65536, 196608, 458752};
    const size_t woff[5] = {0, 8192, 24576, 57344, 122880};
    const int    nchs[5] = {2, 4, 8, 16, 32};
    dim3 gemmGrid(8, 64);

    for (int s = 0; s < 4; s++) {
        gemm_mma_kernel<<<gemmGrid, 128>>>(
            abuf + aoff[s], wbuf + woff[s], nchs[s],
            ybuf + (size_t)s * MROWS * NOUT, stats + (size_t)s * 2048);
    }

    norm_acc4_kernel<<<2048, 256>>>(
        ybuf + 0ull * MROWS * NOUT, ybuf + 1ull * MROWS * NOUT,
        ybuf + 2ull * MROWS * NOUT, ybuf + 3ull * MROWS * NOUT,
        f[4], stats,
        gam[0], gam[1], gam[2], gam[3],
        bet[0], bet[1], bet[2], bet[3],
        accf);

    gemm_mma_kernel<<<gemmGrid, 128>>>(
        accf, wbuf + woff[4], nchs[4], ybuf, stats + 4 * 2048);

    finalize_stats_kernel<<<4, 256>>>(stats + 4 * 2048, gam[4], bet[4]);

    norm_final_kernel<<<CHUNK / 4 / 256, 256>>>(
        (const float4*)ybuf, stats + 4 * 2048,
        (const float4*)f[4], (float4*)(out + (size_t)4 * CHUNK));

    // Join the copy fork before returning.
    cudaStreamWaitEvent(0, g_e2, 0);
}

// round 7
// speedup vs baseline: 5.3293x; 1.1387x over previous
#include <cuda_runtime.h>
#include <cuda_fp16.h>
#include <cstdint>
#include <cstddef>

#define MROWS   8192
#define NOUT    1024
#define CHUNK   8388608
#define SLOPE   0.2f
#define EPSV    1e-5f

// ---------------------------------------------------------------------------
// Scratch (device globals)
// ---------------------------------------------------------------------------
__device__ __half g_ybufh[4u * MROWS * NOUT]; // 64 MB: branch GEMM outputs (fp16)
__device__ float  g_yf32[MROWS * NOUT];       // 32 MB: final GEMM output (fp32)
__device__ uint4  g_abuf[983040];             // branch A' fp16 fragment-major
__device__ uint4  g_accf[1048576];            // stage-5 A' fp16 fragment-major
__device__ uint4  g_wbuf[253952];             // W' fp16 fragment-major (all 5)
__device__ int    g_rows[4 * MROWS];
__device__ float  g_stats[5 * 2 * NOUT];      // raw [sum|sumsq] per stage

// Cached side-streams/events (infra only; captured work identical per call)
static cudaStream_t g_s2 = nullptr, g_s3 = nullptr;
static cudaEvent_t  g_e1 = nullptr, g_e2 = nullptr, g_e3 = nullptr;

// ---------------------------------------------------------------------------
// Helpers
// ---------------------------------------------------------------------------
__device__ __forceinline__ uint32_t smem_u32(const void* p) {
    uint32_t a;
    asm("{ .reg .u64 t; cvta.to.shared.u64 t, %1; cvt.u32.u64 %0, t; }" : "=r"(a) : "l"(p));
    return a;
}
__device__ __forceinline__ uint32_t h2pack(float a, float b) {
    __half2 h = __floats2half2_rn(a, b);
    return *(uint32_t*)&h;
}
__device__ __forceinline__ float4 h4unpack(uint2 v) {
    __half2 a = *(__half2*)&v.x, b = *(__half2*)&v.y;
    float2 fa = __half22float2(a), fb = __half22float2(b);
    return make_float4(fa.x, fa.y, fb.x, fb.y);
}
__device__ __forceinline__ void mma_f16(float c[4], const uint4& a, uint32_t b0, uint32_t b1)
{
    asm volatile(
        "mma.sync.aligned.m16n8k16.row.col.f32.f16.f16.f32 "
        "{%0,%1,%2,%3}, {%4,%5,%6,%7}, {%8,%9}, {%0,%1,%2,%3};\n"
        : "+f"(c[0]), "+f"(c[1]), "+f"(c[2]), "+f"(c[3])
        : "r"(a.x), "r"(a.y), "r"(a.z), "r"(a.w), "r"(b0), "r"(b1));
}
__device__ __forceinline__ float leaky(float v) { return v >= 0.f ? v : SLOPE * v; }

// ---------------------------------------------------------------------------
// Index chains
// ---------------------------------------------------------------------------
__global__ void idx_kernel(const int* __restrict__ F0, const int* __restrict__ F1,
                           const int* __restrict__ F2, const int* __restrict__ F3,
                           int* __restrict__ rows)
{
    int i = blockIdx.x * blockDim.x + threadIdx.x;
    if (i >= MROWS) return;
    int b  = i >> 7;
    int i3 = F3[i];
    int i2 = F2[(b << 8) + i3];
    int i1 = F1[(b << 9) + i2];
    int i0 = F0[(b << 10) + i1];
    rows[0 * MROWS + i] = (b << 11) + i0;
    rows[1 * MROWS + i] = (b << 10) + i1;
    rows[2 * MROWS + i] = (b << 9)  + i2;
    rows[3 * MROWS + i] = (b << 8)  + i3;
}

// ---------------------------------------------------------------------------
// Pass-through copy of f0..f3 -> out slices (runs on a forked stream)
// ---------------------------------------------------------------------------
__global__ void copy4_kernel(const float4* __restrict__ f0, const float4* __restrict__ f1,
                             const float4* __restrict__ f2, const float4* __restrict__ f3,
                             float4* __restrict__ out)
{
    int seg = blockIdx.y;
    size_t i = (size_t)blockIdx.x * 256 + threadIdx.x;
    const float4* src = seg == 0 ? f0 : seg == 1 ? f1 : seg == 2 ? f2 : f3;
    out[(size_t)seg * (CHUNK / 4) + i] = src[i];
}

// ---------------------------------------------------------------------------
// Gather + fp16-convert branch A operands into m16n8k16 fragment-major layout.
// ---------------------------------------------------------------------------
__global__ void gatherA_kernel(const float* __restrict__ f0, const float* __restrict__ f1,
                               const float* __restrict__ f2, const float* __restrict__ f3,
                               const int* __restrict__ rows, uint4* __restrict__ out)
{
    int v = blockIdx.x * 256 + threadIdx.x;   // 0 .. 983039
    int s, base, lognch;
    if      (v < 65536)  { s = 0; base = 0;      lognch = 1; }
    else if (v < 196608) { s = 1; base = 65536;  lognch = 2; }
    else if (v < 458752) { s = 2; base = 196608; lognch = 3; }
    else                 { s = 3; base = 458752; lognch = 4; }
    const float* X = s == 0 ? f0 : s == 1 ? f1 : s == 2 ? f2 : f3;
    const int K = 32 << lognch;
    int lv = v - base;
    int lane = lv & 31, f = (lv >> 5) & 7, wm = (lv >> 8) & 1;
    int mt = f >> 1, ks = f & 1;
    int rest = lv >> 9;
    int kc   = rest & ((1 << lognch) - 1);
    int mblk = rest >> lognch;
    int lg = lane >> 2, lt = lane & 3;
    int gR = mblk * 128 + wm * 64 + mt * 16 + lg;
    const int* rs = rows + s * MROWS;
    int r0 = rs[gR], r1 = rs[gR + 8];
    int c0 = kc * 32 + ks * 16 + lt * 2;
    const float* p0 = X + (size_t)r0 * K + c0;
    const float* p1 = X + (size_t)r1 * K + c0;
    float2 a0 = *(const float2*)p0,       a1 = *(const float2*)p1;
    float2 a2 = *(const float2*)(p0 + 8), a3 = *(const float2*)(p1 + 8);
    uint4 o;
    o.x = h2pack(a0.x, a0.y);
    o.y = h2pack(a1.x, a1.y);
    o.z = h2pack(a2.x, a2.y);
    o.w = h2pack(a3.x, a3.y);
    out[v] = o;
}

// ---------------------------------------------------------------------------
// Convert all 5 weight matrices into fp16 fragment-major B layout.
// ---------------------------------------------------------------------------
__global__ void convW_kernel(const float* __restrict__ w0, const float* __restrict__ w1,
                             const float* __restrict__ w2, const float* __restrict__ w3,
                             const float* __restrict__ w4, uint4* __restrict__ out)
{
    int v = blockIdx.x * 256 + threadIdx.x;   // 0 .. 253951
    int s, base, lognch;
    if      (v < 8192)   { s = 0; base = 0;      lognch = 1; }
    else if (v < 24576)  { s = 1; base = 8192;   lognch = 2; }
    else if (v < 57344)  { s = 2; base = 24576;  lognch = 3; }
    else if (v < 122880) { s = 3; base = 57344;  lognch = 4; }
    else                 { s = 4; base = 122880; lognch = 5; }
    const float* W = s == 0 ? w0 : s == 1 ? w1 : s == 2 ? w2 : s == 3 ? w3 : w4;
    const int K = 32 << lognch;
    int lv = v - base;
    int lane = lv & 31, nt = (lv >> 5) & 7, wn = (lv >> 8) & 1;
    int rest = lv >> 9;
    int kc   = rest & ((1 << lognch) - 1);
    int nblk = rest >> lognch;
    int lg = lane >> 2, lt = lane & 3;
    int col = nblk * 128 + wn * 64 + nt * 8 + lg;
    const float* wr = W + (size_t)col * K + kc * 32 + lt * 2;
    float2 b0 = *(const float2*)wr;
    float2 b1 = *(const float2*)(wr + 8);
    float2 b2 = *(const float2*)(wr + 16);
    float2 b3 = *(const float2*)(wr + 24);
    uint4 o;
    o.x = h2pack(b0.x, b0.y);
    o.y = h2pack(b1.x, b1.y);
    o.z = h2pack(b2.x, b2.y);
    o.w = h2pack(b3.x, b3.y);
    out[v] = o;
}

// ---------------------------------------------------------------------------
// GEMM core (shared by branch + final kernels)
// CTA 128x128, 4 warps (2m x 2n of 64x64), BK=32, 3-stage cp.async pipeline.
// ---------------------------------------------------------------------------
struct GemmCtx {
    float c[4][8][4];
    int lane, wm, wn, lg, lt;
};

__device__ __forceinline__ void gemm_core(
    const uint4* __restrict__ Ag, const uint4* __restrict__ Bg,
    int nch, uint4 (*sm)[1024], GemmCtx& gc, int tid)
{
    const uint32_t sb = smem_u32(sm);
#pragma unroll
    for (int mt = 0; mt < 4; mt++)
#pragma unroll
        for (int nt = 0; nt < 8; nt++)
#pragma unroll
            for (int j = 0; j < 4; j++) gc.c[mt][nt][j] = 0.f;

    int fetch = 0;
#pragma unroll
    for (int p = 0; p < 2; p++) {
        if (fetch < nch) {
            const uint4* as = Ag + (size_t)fetch * 512 + tid;
            const uint4* bs = Bg + (size_t)fetch * 512 + tid;
            uint32_t da = sb + (uint32_t)(p * 1024 + tid) * 16;
#pragma unroll
            for (int i = 0; i < 4; i++) {
                asm volatile("cp.async.cg.shared.global [%0], [%1], 16;" :: "r"(da + i * 2048), "l"(as + i * 128));
                asm volatile("cp.async.cg.shared.global [%0], [%1], 16;" :: "r"(da + 8192 + i * 2048), "l"(bs + i * 128));
            }
        }
        asm volatile("cp.async.commit_group;");
        fetch++;
    }

    int cs = 0, fs = 2;
    for (int ch = 0; ch < nch; ch++) {
        asm volatile("cp.async.wait_group 1;");
        __syncthreads();
        const uint4* As = sm[cs];
        const uint4* Bs = sm[cs] + 512;

        uint4 aq[8], bq[8];
#pragma unroll
        for (int f = 0; f < 8; f++) aq[f] = As[(gc.wm * 8 + f) * 32 + gc.lane];
#pragma unroll
        for (int nt = 0; nt < 8; nt++) bq[nt] = Bs[(gc.wn * 8 + nt) * 32 + gc.lane];

#pragma unroll
        for (int ks = 0; ks < 2; ks++)
#pragma unroll
            for (int mt = 0; mt < 4; mt++) {
                const uint4& a = aq[mt * 2 + ks];
#pragma unroll
                for (int nt = 0; nt < 8; nt++) {
                    uint32_t b0 = ks ? bq[nt].z : bq[nt].x;
                    uint32_t b1 = ks ? bq[nt].w : bq[nt].y;
                    mma_f16(gc.c[mt][nt], a, b0, b1);
                }
            }

        if (fetch < nch) {
            const uint4* as = Ag + (size_t)fetch * 512 + tid;
            const uint4* bs = Bg + (size_t)fetch * 512 + tid;
            uint32_t da = sb + (uint32_t)(fs * 1024 + tid) * 16;
#pragma unroll
            for (int i = 0; i < 4; i++) {
                asm volatile("cp.async.cg.shared.global [%0], [%1], 16;" :: "r"(da + i * 2048), "l"(as + i * 128));
                asm volatile("cp.async.cg.shared.global [%0], [%1], 16;" :: "r"(da + 8192 + i * 2048), "l"(bs + i * 128));
            }
        }
        asm volatile("cp.async.commit_group;");
        fetch++;
        if (++cs == 3) cs = 0;
        if (++fs == 3) fs = 0;
    }
}

__device__ __forceinline__ void gemm_stats(const GemmCtx& gc, int bn, float* __restrict__ st)
{
#pragma unroll
    for (int nt = 0; nt < 8; nt++) {
        float s0 = 0.f, s1 = 0.f, q0 = 0.f, q1 = 0.f;
#pragma unroll
        for (int mt = 0; mt < 4; mt++) {
            float e0 = gc.c[mt][nt][0], e1 = gc.c[mt][nt][1];
            float e2 = gc.c[mt][nt][2], e3 = gc.c[mt][nt][3];
            s0 += e0 + e2; s1 += e1 + e3;
            q0 += e0 * e0 + e2 * e2;
            q1 += e1 * e1 + e3 * e3;
        }
#pragma unroll
        for (int off = 4; off < 32; off <<= 1) {
            s0 += __shfl_xor_sync(0xffffffffu, s0, off);
            s1 += __shfl_xor_sync(0xffffffffu, s1, off);
            q0 += __shfl_xor_sync(0xffffffffu, q0, off);
            q1 += __shfl_xor_sync(0xffffffffu, q1, off);
        }
        if (gc.lane < 4) {
            int col = bn * 128 + gc.wn * 64 + nt * 8 + gc.lane * 2;
            atomicAdd(&st[col],            s0);
            atomicAdd(&st[col + 1],        s1);
            atomicAdd(&st[NOUT + col],     q0);
            atomicAdd(&st[NOUT + col + 1], q1);
        }
    }
}

// ---------------------------------------------------------------------------
// All 4 branch GEMMs in one launch (blockIdx.z = stage). Y in fp16.
// ---------------------------------------------------------------------------
__global__ __launch_bounds__(128, 2) void gemm_branch_kernel(
    const uint4* __restrict__ A, const uint4* __restrict__ B,
    __half* __restrict__ Yh, float* __restrict__ stats)
{
    __shared__ uint4 sm[3][1024];
    const int tid = threadIdx.x;
    const int s = blockIdx.z;
    const int nchs[4]  = {2, 4, 8, 16};
    const int aoff[4]  = {0, 65536, 196608, 458752};
    const int woff[4]  = {0, 8192, 24576, 57344};
    const int nch = nchs[s];
    const int bn = blockIdx.x, bm = blockIdx.y;

    GemmCtx gc;
    gc.lane = tid & 31;
    int wid = tid >> 5;
    gc.wm = wid & 1; gc.wn = wid >> 1;
    gc.lg = gc.lane >> 2; gc.lt = gc.lane & 3;

    gemm_core(A + (size_t)aoff[s] + (size_t)bm * nch * 512,
              B + (size_t)woff[s] + (size_t)bn * nch * 512,
              nch, sm, gc, tid);

    __half* Y = Yh + (size_t)s * MROWS * NOUT;
    const int rowbase = bm * 128 + gc.wm * 64 + gc.lg;
    const int colbase = bn * 128 + gc.wn * 64 + gc.lt * 2;
#pragma unroll
    for (int mt = 0; mt < 4; mt++) {
        const int r0 = rowbase + mt * 16;
#pragma unroll
        for (int nt = 0; nt < 8; nt++) {
            const int cc = colbase + nt * 8;
            *(uint32_t*)&Y[(size_t)r0 * NOUT + cc]       = h2pack(gc.c[mt][nt][0], gc.c[mt][nt][1]);
            *(uint32_t*)&Y[(size_t)(r0 + 8) * NOUT + cc] = h2pack(gc.c[mt][nt][2], gc.c[mt][nt][3]);
        }
    }
    gemm_stats(gc, bn, stats + (size_t)s * 2048);
}

// ---------------------------------------------------------------------------
// Final GEMM (K=1024), fp32 Y output + fused stats.
// ---------------------------------------------------------------------------
__global__ __launch_bounds__(128, 2) void gemm_final_kernel(
    const uint4* __restrict__ A, const uint4* __restrict__ B,
    float* __restrict__ Y, float* __restrict__ st)
{
    __shared__ uint4 sm[3][1024];
    const int tid = threadIdx.x;
    const int bn = blockIdx.x, bm = blockIdx.y;
    const int nch = 32;

    GemmCtx gc;
    gc.lane = tid & 31;
    int wid = tid >> 5;
    gc.wm = wid & 1; gc.wn = wid >> 1;
    gc.lg = gc.lane >> 2; gc.lt = gc.lane & 3;

    gemm_core(A + (size_t)bm * nch * 512, B + (size_t)bn * nch * 512, nch, sm, gc, tid);

    const int rowbase = bm * 128 + gc.wm * 64 + gc.lg;
    const int colbase = bn * 128 + gc.wn * 64 + gc.lt * 2;
#pragma unroll
    for (int mt = 0; mt < 4; mt++) {
        const int r0 = rowbase + mt * 16;
#pragma unroll
        for (int nt = 0; nt < 8; nt++) {
            const int cc = colbase + nt * 8;
            *(float2*)&Y[(size_t)r0 * NOUT + cc]       = make_float2(gc.c[mt][nt][0], gc.c[mt][nt][1]);
            *(float2*)&Y[(size_t)(r0 + 8) * NOUT + cc] = make_float2(gc.c[mt][nt][2], gc.c[mt][nt][3]);
        }
    }
    gemm_stats(gc, bn, st);
}

// ---------------------------------------------------------------------------
// Fused: finalize BN stages 0-3 + acc = f4 + sum leaky(norm(y_s)) -> fp16
// fragment-major stage-5 A operand. Grid 2048 (64 mblk x 32 kc), block 256.
// ---------------------------------------------------------------------------
__global__ __launch_bounds__(256) void norm_acc4_kernel(
    const __half* __restrict__ yh,
    const float* __restrict__ f4,
    const float* __restrict__ stats,
    const float* __restrict__ g0, const float* __restrict__ g1,
    const float* __restrict__ g2, const float* __restrict__ g3,
    const float* __restrict__ be0, const float* __restrict__ be1,
    const float* __restrict__ be2, const float* __restrict__ be3,
    uint4* __restrict__ accf)
{
    __shared__ float smt[128 * 36];
    __shared__ float scsh[4][2][32];
    const int mblk = blockIdx.x >> 5;
    const int kc   = blockIdx.x & 31;
    const int tid  = threadIdx.x;

    if (tid < 128) {
        int s = tid >> 5, lc = tid & 31;
        const float* st = stats + s * 2048;
        int ch = kc * 32 + lc;
        const float* gp  = s == 0 ? g0  : s == 1 ? g1  : s == 2 ? g2  : g3;
        const float* bep = s == 0 ? be0 : s == 1 ? be1 : s == 2 ? be2 : be3;
        const float inv = 1.0f / (float)MROWS;
        float mean = st[ch] * inv;
        float var  = st[NOUT + ch] * inv - mean * mean;
        float sc   = rsqrtf(var + EPSV) * gp[ch];
        scsh[s][0][lc] = sc;
        scsh[s][1][lc] = bep[ch] - mean * sc;
    }
    __syncthreads();

#pragma unroll
    for (int i = 0; i < 4; i++) {
        int v = tid + 256 * i;          // 0..1023 quads of the 128x32 chunk
        int r = v >> 3, cq = (v & 7) * 4;
        size_t off = ((size_t)(mblk * 128 + r)) * NOUT + kc * 32 + cq;
        float4 a = *(const float4*)(f4 + off);
#pragma unroll
        for (int s = 0; s < 4; s++) {
            float4 y = h4unpack(*(const uint2*)(yh + (size_t)s * MROWS * NOUT + off));
            a.x += leaky(y.x * scsh[s][0][cq + 0] + scsh[s][1][cq + 0]);
            a.y += leaky(y.y * scsh[s][0][cq + 1] + scsh[s][1][cq + 1]);
            a.z += leaky(y.z * scsh[s][0][cq + 2] + scsh[s][1][cq + 2]);
            a.w += leaky(y.w * scsh[s][0][cq + 3] + scsh[s][1][cq + 3]);
        }
        *(float4*)&smt[r * 36 + cq] = a;
    }
    __syncthreads();

#pragma unroll
    for (int i = 0; i < 2; i++) {
        int o = tid + 256 * i;          // 0..511 fragment uint4 in this chunk
        int lane = o & 31, f = (o >> 5) & 7, wm = (o >> 8) & 1;
        int mt = f >> 1, ks = f & 1;
        int lg = lane >> 2, lt = lane & 3;
        int r0 = wm * 64 + mt * 16 + lg;
        int c0 = ks * 16 + lt * 2;
        uint4 w;
        w.x = h2pack(smt[r0 * 36 + c0],       smt[r0 * 36 + c0 + 1]);
        w.y = h2pack(smt[(r0 + 8) * 36 + c0], smt[(r0 + 8) * 36 + c0 + 1]);
        w.z = h2pack(smt[r0 * 36 + c0 + 8],       smt[r0 * 36 + c0 + 9]);
        w.w = h2pack(smt[(r0 + 8) * 36 + c0 + 8], smt[(r0 + 8) * 36 + c0 + 9]);
        accf[((size_t)(mblk * 32 + kc)) * 512 + o] = w;
    }
}

// ---------------------------------------------------------------------------
// Finalize stage-4 stats (in place)
// ---------------------------------------------------------------------------
__global__ void finalize_stats_kernel(float* __restrict__ st,
                                      const float* __restrict__ g,
                                      const float* __restrict__ be)
{
    int c = blockIdx.x * blockDim.x + threadIdx.x;
    if (c >= NOUT) return;
    const float inv = 1.0f / (float)MROWS;
    float mean = st[c] * inv;
    float var  = st[NOUT + c] * inv - mean * mean;
    float sc   = rsqrtf(var + EPSV) * g[c];
    st[c]        = sc;
    st[NOUT + c] = be[c] - mean * sc;
}

// out = leaky(y * sc + sh) + f4
__global__ void norm_final_kernel(const float4* __restrict__ Y,
                                  const float* __restrict__ st,
                                  const float4* __restrict__ f4,
                                  float4* __restrict__ out)
{
    int i = blockIdx.x * blockDim.x + threadIdx.x;
    int c4 = i & 255;
    float4 sc = ((const float4*)st)[c4];
    float4 sh = ((const float4*)(st + NOUT))[c4];
    float4 y = Y[i];
    float4 r = f4[i];
    float4 o;
    o.x = leaky(y.x * sc.x + sh.x) + r.x;
    o.y = leaky(y.y * sc.y + sh.y) + r.y;
    o.z = leaky(y.z * sc.z + sh.z) + r.z;
    o.w = leaky(y.w * sc.w + sh.w) + r.w;
    out[i] = o;
}

// ---------------------------------------------------------------------------
// Host launcher
// ---------------------------------------------------------------------------
extern "C" void kernel_launch(void* const* d_in, const int* in_sizes, int n_in,
                              void* d_out, int out_size)
{
    (void)in_sizes; (void)n_in; (void)out_size;

    const float* f[5];
    for (int i = 0; i < 5; i++) f[i] = (const float*)d_in[1 + i];
    const int* FPS[4];
    for (int i = 0; i < 4; i++) FPS[i] = (const int*)d_in[6 + i];

    const float* w[5]; const float* gam[5]; const float* bet[5];
    for (int i = 0; i < 5; i++) {
        w[i]   = (const float*)d_in[10 + 4 * i + 0];
        gam[i] = (const float*)d_in[10 + 4 * i + 2];
        bet[i] = (const float*)d_in[10 + 4 * i + 3];
    }

    float* out = (float*)d_out;

    float *yf32, *stats;
    __half *ybufh;
    uint4 *abuf, *accf, *wbuf;
    int   *rows;
    cudaGetSymbolAddress((void**)&ybufh, g_ybufh);
    cudaGetSymbolAddress((void**)&yf32,  g_yf32);
    cudaGetSymbolAddress((void**)&abuf,  g_abuf);
    cudaGetSymbolAddress((void**)&accf,  g_accf);
    cudaGetSymbolAddress((void**)&wbuf,  g_wbuf);
    cudaGetSymbolAddress((void**)&stats, g_stats);
    cudaGetSymbolAddress((void**)&rows,  g_rows);

    if (!g_s2) {
        cudaStreamCreateWithFlags(&g_s2, cudaStreamNonBlocking);
        cudaStreamCreateWithFlags(&g_s3, cudaStreamNonBlocking);
        cudaEventCreateWithFlags(&g_e1, cudaEventDisableTiming);
        cudaEventCreateWithFlags(&g_e2, cudaEventDisableTiming);
        cudaEventCreateWithFlags(&g_e3, cudaEventDisableTiming);
    }

    // Fork point
    cudaEventRecord(g_e1, 0);

    // Stream 2: pass-through copies (independent of everything else)
    cudaStreamWaitEvent(g_s2, g_e1, 0);
    copy4_kernel<<<dim3(CHUNK / 4 / 256, 4), 256, 0, g_s2>>>(
        (const float4*)f[0], (const float4*)f[1],
        (const float4*)f[2], (const float4*)f[3], (float4*)out);
    cudaEventRecord(g_e2, g_s2);

    // Stream 3: weight conversion (independent of index chain)
    cudaStreamWaitEvent(g_s3, g_e1, 0);
    convW_kernel<<<992, 256, 0, g_s3>>>(w[0], w[1], w[2], w[3], w[4], wbuf);
    cudaEventRecord(g_e3, g_s3);

    // Main chain
    cudaMemsetAsync(stats, 0, 5 * 2 * NOUT * sizeof(float), 0);
    idx_kernel<<<MROWS / 256, 256>>>(FPS[0], FPS[1], FPS[2], FPS[3], rows);
    gatherA_kernel<<<3840, 256>>>(f[0], f[1], f[2], f[3], rows, abuf);
    cudaStreamWaitEvent(0, g_e3, 0);

    // All 4 branch GEMMs in one launch
    gemm_branch_kernel<<<dim3(8, 64, 4), 128>>>(abuf, wbuf, ybufh, stats);

    norm_acc4_kernel<<<2048, 256>>>(
        ybufh, f[4], stats,
        gam[0], gam[1], gam[2], gam[3],
        bet[0], bet[1], bet[2], bet[3],
        accf);

    gemm_final_kernel<<<dim3(8, 64), 128>>>(accf, wbuf + 122880, yf32, stats + 4 * 2048);

    finalize_stats_kernel<<<4, 256>>>(stats + 4 * 2048, gam[4], bet[4]);

    norm_final_kernel<<<CHUNK / 4 / 256, 256>>>(
        (const float4*)yf32, stats + 4 * 2048,
        (const float4*)f[4], (float4*)(out + (size_t)4 * CHUNK));

    // Join the copy fork
    cudaStreamWaitEvent(0, g_e2, 0);
}